// round 15
// baseline (speedup 1.0000x reference)
#include <cuda_runtime.h>
#include <cuda_fp16.h>
#include <math.h>
#include <stdint.h>

// ---------------- problem constants ----------------
#define B_     2
#define C_     256
#define N_     32768
#define H_     128
#define W_     128
#define HW_    16384
#define NG_    3
#define DEPTH_ 4
#define NCELLS (B_*NG_*HW_)    // 98304 = 384*256

// ---------------- device scratch (static, no allocs) ----------------
__device__ float g_grid2 [B_*HW_*C_];
__device__ float g_plane2[B_*HW_*C_];
__device__ float g_skip2 [B_*HW_*C_];
__device__ float g_tok2  [(size_t)B_*N_*C_];
__device__ float g_wpt  [B_*NG_*N_];
__device__ int   g_ci   [B_*NG_*N_];
__device__ float g_counts[B_*NG_*HW_];
__device__ int   g_cnt [NCELLS];
__device__ int   g_off [NCELLS];
__device__ int   g_fill[NCELLS];
__device__ int   g_bsum[384];
__device__ int   g_bpre[384];
__device__ int   g_csr [B_*NG_*N_];
__device__ float g_bn_sum[C_];
__device__ float g_bn_sq [C_];
__device__ float2 g_murs[B_*N_];
__device__ __half g_h[(size_t)B_*N_*C_];

// ---------------- helpers ----------------
__device__ __forceinline__ void mma_f16(float d[4], const uint32_t a[4], const uint32_t b[2]) {
    asm volatile(
        "mma.sync.aligned.m16n8k16.row.col.f32.f16.f16.f32 "
        "{%0,%1,%2,%3}, {%4,%5,%6,%7}, {%8,%9}, {%0,%1,%2,%3};\n"
        : "+f"(d[0]), "+f"(d[1]), "+f"(d[2]), "+f"(d[3])
        : "r"(a[0]), "r"(a[1]), "r"(a[2]), "r"(a[3]),
          "r"(b[0]), "r"(b[1]));
}

// ---------------- tiled transpose ----------------
__global__ void transpose_kernel(const float* __restrict__ src, float* __restrict__ dst,
                                 int R, int Cc) {
    __shared__ float t[32][33];
    int b = blockIdx.z;
    const float* s = src + (size_t)b*R*Cc;
    float* d = dst + (size_t)b*R*Cc;
    int c0 = blockIdx.x * 32;
    int r0 = blockIdx.y * 32;
    int tx = threadIdx.x, ty = threadIdx.y;
    #pragma unroll
    for (int i = ty; i < 32; i += 8)
        t[i][tx] = s[(size_t)(r0+i)*Cc + c0 + tx];
    __syncthreads();
    #pragma unroll
    for (int i = ty; i < 32; i += 8)
        d[(size_t)(c0+i)*R + r0 + tx] = t[tx][i];
}

// ---------------- projection weights + CSR build (once) ----------------
__global__ void zero_counts_kernel() {
    int i = blockIdx.x * blockDim.x + threadIdx.x;
    if (i < NCELLS) { g_counts[i] = 0.f; g_cnt[i] = 0; g_fill[i] = 0; }
}
__global__ void count_scatter_kernel(const int* __restrict__ cell_ind,
                                     const float* __restrict__ occ) {
    int i = blockIdx.x * blockDim.x + threadIdx.x;
    if (i >= B_*NG_*N_) return;
    int n = i % N_;
    int b = i / (NG_*N_);
    int ci = cell_ind[i];
    ci = min(max(ci, 0), HW_ - 1);
    g_ci[i] = ci;
    float o = occ[b*N_ + n];
    int cellflat = (i / N_)*HW_ + ci;
    atomicAdd(&g_counts[cellflat], o*o);
    atomicAdd(&g_cnt[cellflat], 1);
}
__global__ void wpt_kernel(const float* __restrict__ occ) {
    int i = blockIdx.x * blockDim.x + threadIdx.x;
    if (i >= B_*NG_*N_) return;
    int n = i % N_;
    int b = i / (NG_*N_);
    float o = occ[b*N_ + n];
    float cnt = g_counts[(i / N_)*HW_ + g_ci[i]];
    g_wpt[i] = o / (o*cnt + 1e-6f);
}
__global__ void scan1_kernel() {
    __shared__ int s[256];
    int i = blockIdx.x*256 + threadIdx.x;
    int v = g_cnt[i];
    s[threadIdx.x] = v;
    __syncthreads();
    #pragma unroll
    for (int o = 1; o < 256; o <<= 1) {
        int t = (threadIdx.x >= o) ? s[threadIdx.x - o] : 0;
        __syncthreads();
        s[threadIdx.x] += t;
        __syncthreads();
    }
    g_off[i] = s[threadIdx.x] - v;
    if (threadIdx.x == 255) g_bsum[blockIdx.x] = s[255];
}
__global__ void scan2_kernel() {
    __shared__ int s[512];
    int t = threadIdx.x;
    int v = (t < 384) ? g_bsum[t] : 0;
    s[t] = v;
    __syncthreads();
    #pragma unroll
    for (int o = 1; o < 512; o <<= 1) {
        int u = (t >= o) ? s[t - o] : 0;
        __syncthreads();
        s[t] += u;
        __syncthreads();
    }
    if (t < 384) g_bpre[t] = s[t] - v;
}
__global__ void scan3_kernel() {
    int i = blockIdx.x*256 + threadIdx.x;
    g_off[i] += g_bpre[blockIdx.x];
}
__global__ void fill_csr_kernel() {
    int i = blockIdx.x * blockDim.x + threadIdx.x;
    if (i >= B_*NG_*N_) return;
    int n = i % N_;
    int cellflat = (i / N_)*HW_ + g_ci[i];
    int slot = atomicAdd(&g_fill[cellflat], 1);
    g_csr[g_off[cellflat] + slot] = n;
}

// ---------------- SpatialMix: CSR warp-per-cell LN + single coalesced write ----------------
__global__ void ln_scatter_csr(const float* __restrict__ lng,
                               const float* __restrict__ lnb,
                               int g) {
    __shared__ float4 sg[64], sb[64];
    int tid = threadIdx.x;
    if (blockIdx.x == 0 && blockIdx.y == 0) {
        g_bn_sum[tid] = 0.f;
        g_bn_sq[tid]  = 0.f;
    }
    if (tid < 64) {
        sg[tid] = reinterpret_cast<const float4*>(lng)[tid];
        sb[tid] = reinterpret_cast<const float4*>(lnb)[tid];
    }
    __syncthreads();

    int lane = tid & 31;
    int cell = blockIdx.x * 8 + (tid >> 5);
    int b = blockIdx.y;
    int cellflat = (b*NG_ + g)*HW_ + cell;
    int cnt = g_cnt[cellflat];
    int off = g_off[cellflat];

    float4 a0 = make_float4(0.f,0.f,0.f,0.f);
    float4 a1 = make_float4(0.f,0.f,0.f,0.f);
    float4 lg0 = sg[lane],      lb0 = sb[lane];
    float4 lg1 = sg[32 + lane], lb1 = sb[32 + lane];

    for (int k = 0; k < cnt; k++) {
        int n = g_csr[off + k];
        const float4* row = reinterpret_cast<const float4*>(g_tok2 + ((size_t)b*N_ + n)*C_);
        float4 v0 = row[lane];
        float4 v1 = row[32 + lane];
        float s  = v0.x + v0.y + v0.z + v0.w + v1.x + v1.y + v1.z + v1.w;
        float ss = v0.x*v0.x + v0.y*v0.y + v0.z*v0.z + v0.w*v0.w
                 + v1.x*v1.x + v1.y*v1.y + v1.z*v1.z + v1.w*v1.w;
        #pragma unroll
        for (int o = 16; o > 0; o >>= 1) {
            s  += __shfl_xor_sync(0xFFFFFFFFu, s,  o);
            ss += __shfl_xor_sync(0xFFFFFFFFu, ss, o);
        }
        float m    = s * (1.f / C_);
        float rstd = rsqrtf(ss * (1.f / C_) - m*m + 1e-5f);
        float w    = g_wpt[((size_t)b*NG_ + g)*N_ + n];

        a0.x += ((v0.x - m)*rstd*lg0.x + lb0.x)*w;
        a0.y += ((v0.y - m)*rstd*lg0.y + lb0.y)*w;
        a0.z += ((v0.z - m)*rstd*lg0.z + lb0.z)*w;
        a0.w += ((v0.w - m)*rstd*lg0.w + lb0.w)*w;
        a1.x += ((v1.x - m)*rstd*lg1.x + lb1.x)*w;
        a1.y += ((v1.y - m)*rstd*lg1.y + lb1.y)*w;
        a1.z += ((v1.z - m)*rstd*lg1.z + lb1.z)*w;
        a1.w += ((v1.w - m)*rstd*lg1.w + lb1.w)*w;
    }
    float4* gb = reinterpret_cast<float4*>(g_grid2 + ((size_t)b*HW_ + cell)*C_);
    gb[lane]      = a0;
    gb[32 + lane] = a1;
}

// ---------------- channel-last fused dwconv3x3 -> relu -> dwconv3x3 (+BN, +skip) ----------------
#define CONV_CL_SMEM ((400*32 + 324*32 + 288*2 + 64 + 64) * 4)
__global__ void __launch_bounds__(256, 2)
conv_cl_kernel(const float* __restrict__ w1g, const float* __restrict__ b1g,
               const float* __restrict__ w2g, const float* __restrict__ b2g,
               int save_skip, int add_skip) {
    extern __shared__ float cs[];
    float* sIn  = cs;
    float* sMid = sIn + 400*32;
    float* sW1  = sMid + 324*32;
    float* sW2  = sW1 + 288;
    float* sB   = sW2 + 288;
    float* bnS  = sB + 64;
    float* bnQ  = bnS + 32;

    const int tid = threadIdx.x;
    const int cq  = tid & 7;
    const int pp  = tid >> 3;
    const int cg0 = blockIdx.y * 32;
    const int b   = blockIdx.z;
    const int oy  = (blockIdx.x >> 3) * 16;
    const int ox  = (blockIdx.x & 7) * 16;

    for (int i = tid; i < 288; i += 256) {
        int k = i >> 5, cc = i & 31;
        sW1[k*32 + cc] = w1g[(cg0+cc)*9 + k];
        sW2[k*32 + cc] = w2g[(cg0+cc)*9 + k];
    }
    if (tid < 32) {
        sB[tid]      = b1g[cg0 + tid];
        sB[32 + tid] = b2g[cg0 + tid];
        bnS[tid] = 0.f;
        bnQ[tid] = 0.f;
    }

    for (int i = pp; i < 400; i += 32) {
        int py = i / 20, px = i % 20;
        int gy = oy + py - 2, gx = ox + px - 2;
        float4 v = make_float4(0.f, 0.f, 0.f, 0.f);
        if (gy >= 0 && gy < H_ && gx >= 0 && gx < W_) {
            size_t off = ((size_t)b*HW_ + gy*W_ + gx)*C_ + cg0 + cq*4;
            v = *reinterpret_cast<const float4*>(g_grid2 + off);
            if (add_skip) {
                float4 s = *reinterpret_cast<const float4*>(g_skip2 + off);
                v.x += s.x; v.y += s.y; v.z += s.z; v.w += s.w;
            }
        }
        *reinterpret_cast<float4*>(sIn + i*32 + cq*4) = v;
    }
    float4 w1r[9];
    #pragma unroll
    for (int k = 0; k < 9; k++) w1r[k] = *reinterpret_cast<float4*>(sW1 + k*32 + cq*4);
    float4 b1v = *reinterpret_cast<float4*>(sB + cq*4);
    __syncthreads();

    for (int i = pp; i < 324; i += 32) {
        int my = i / 18, mx = i % 18;
        int gy = oy + my - 1, gx = ox + mx - 1;
        float4 acc = make_float4(0.f, 0.f, 0.f, 0.f);
        if (gy >= 0 && gy < H_ && gx >= 0 && gx < W_) {
            acc = b1v;
            #pragma unroll
            for (int ky = 0; ky < 3; ky++)
                #pragma unroll
                for (int kx = 0; kx < 3; kx++) {
                    const float4 u = *reinterpret_cast<float4*>(
                        sIn + ((my+ky)*20 + (mx+kx))*32 + cq*4);
                    const float4 wv = w1r[ky*3+kx];
                    acc.x += wv.x*u.x; acc.y += wv.y*u.y;
                    acc.z += wv.z*u.z; acc.w += wv.w*u.w;
                }
            acc.x = fmaxf(acc.x, 0.f); acc.y = fmaxf(acc.y, 0.f);
            acc.z = fmaxf(acc.z, 0.f); acc.w = fmaxf(acc.w, 0.f);
        }
        *reinterpret_cast<float4*>(sMid + i*32 + cq*4) = acc;
    }
    float4 w2r[9];
    #pragma unroll
    for (int k = 0; k < 9; k++) w2r[k] = *reinterpret_cast<float4*>(sW2 + k*32 + cq*4);
    float4 b2v = *reinterpret_cast<float4*>(sB + 32 + cq*4);
    __syncthreads();

    float4 psum = make_float4(0.f,0.f,0.f,0.f);
    float4 psq  = make_float4(0.f,0.f,0.f,0.f);
    for (int i = pp; i < 256; i += 32) {
        int dy = i >> 4, dx = i & 15;
        float4 acc = b2v;
        #pragma unroll
        for (int ky = 0; ky < 3; ky++)
            #pragma unroll
            for (int kx = 0; kx < 3; kx++) {
                const float4 u = *reinterpret_cast<float4*>(
                    sMid + ((dy+ky)*18 + (dx+kx))*32 + cq*4);
                const float4 wv = w2r[ky*3+kx];
                acc.x += wv.x*u.x; acc.y += wv.y*u.y;
                acc.z += wv.z*u.z; acc.w += wv.w*u.w;
            }
        size_t off = ((size_t)b*HW_ + (oy+dy)*W_ + ox+dx)*C_ + cg0 + cq*4;
        *reinterpret_cast<float4*>(g_plane2 + off) = acc;
        if (save_skip) *reinterpret_cast<float4*>(g_skip2 + off) = acc;
        psum.x += acc.x; psum.y += acc.y; psum.z += acc.z; psum.w += acc.w;
        psq.x += acc.x*acc.x; psq.y += acc.y*acc.y;
        psq.z += acc.z*acc.z; psq.w += acc.w*acc.w;
    }
    atomicAdd(&bnS[cq*4+0], psum.x); atomicAdd(&bnQ[cq*4+0], psq.x);
    atomicAdd(&bnS[cq*4+1], psum.y); atomicAdd(&bnQ[cq*4+1], psq.y);
    atomicAdd(&bnS[cq*4+2], psum.z); atomicAdd(&bnQ[cq*4+2], psq.z);
    atomicAdd(&bnS[cq*4+3], psum.w); atomicAdd(&bnQ[cq*4+3], psq.w);
    __syncthreads();
    if (tid < 32) {
        atomicAdd(&g_bn_sum[cg0 + tid], bnS[tid]);
        atomicAdd(&g_bn_sq [cg0 + tid], bnQ[tid]);
    }
}

// ---------------- gather: folded BN affine + gate + residual + CM LN stats ----------------
__global__ void gather_v3(int g,
                          const float* __restrict__ ascale,
                          const float* __restrict__ bng,
                          const float* __restrict__ bnb) {
    __shared__ float sA[C_], sB2[C_];
    int tid = threadIdx.x;
    {
        int c = tid;
        float s = __ldg(ascale + c);
        float m = g_bn_sum[c] * (1.f / (B_*HW_));
        float v = g_bn_sq[c]  * (1.f / (B_*HW_)) - m*m;
        float r = rsqrtf(s*s*v + 1e-5f);
        float gm = __ldg(bng + c);
        sA[c]  = s * r * gm;
        sB2[c] = __ldg(bnb + c) - s * m * r * gm;
    }
    __syncthreads();

    int lane = tid & 31;
    int n = blockIdx.x * 8 + (tid >> 5);
    int b = blockIdx.y;

    int cell = g_ci[((size_t)b*NG_ + g)*N_ + n];
    const float* pr = g_plane2 + ((size_t)b*HW_ + cell)*C_;
    float* tr = g_tok2 + ((size_t)b*N_ + n)*C_;

    int c0 = lane * 4;
    float s = 0.f, ss = 0.f;
    #pragma unroll
    for (int h = 0; h < 2; h++) {
        int c = c0 + h*128;
        float4 p = *reinterpret_cast<const float4*>(pr + c);
        float4 A = *reinterpret_cast<const float4*>(sA + c);
        float4 Bv = *reinterpret_cast<const float4*>(sB2 + c);
        float4 t = *reinterpret_cast<const float4*>(tr + c);
        t.x += p.x / (1.f + expf(-(p.x*A.x + Bv.x)));
        t.y += p.y / (1.f + expf(-(p.y*A.y + Bv.y)));
        t.z += p.z / (1.f + expf(-(p.z*A.z + Bv.z)));
        t.w += p.w / (1.f + expf(-(p.w*A.w + Bv.w)));
        s  += t.x + t.y + t.z + t.w;
        ss += t.x*t.x + t.y*t.y + t.z*t.z + t.w*t.w;
        *reinterpret_cast<float4*>(tr + c) = t;
    }
    #pragma unroll
    for (int o = 16; o > 0; o >>= 1) {
        s  += __shfl_xor_sync(0xFFFFFFFFu, s,  o);
        ss += __shfl_xor_sync(0xFFFFFFFFu, ss, o);
    }
    if (lane == 0) {
        float m = s * (1.f / C_);
        g_murs[(size_t)b*N_ + n] = make_float2(m, rsqrtf(ss * (1.f / C_) - m*m + 1e-5f));
    }
}

// ======================================================================
// ChannelMix, DUAL-PIPE: 384 threads/CTA.
//   warps 0-7 : HMMA, warp tile 32m x 48n (tokens 0-47), acc[2][6][4]
//   warps 8-11: FFMA, tokens 48-63 x all 256 ch; thread = 8 ch (stride 32,
//               conflict-free W LDS) x 4 tok, fp32 accumulate of half2 pairs.
// Both read the same fp16 Xs/Wh (stride-132-u32 rows, bank = 4*gid+tig).
// ======================================================================
#define WH_STRIDE  132
#define XROW_H     (2*WH_STRIDE)     // halves per row (264)
#define TILES_PB   (N_/64)
#define CM_GRIDX   74
#define CM_THREADS 384
#define HT_        48                // tokens handled by HMMA
#define CM1_SMEM   ((256*WH_STRIDE + 64*WH_STRIDE + 64 + 64 + 256 + 256) * 4)
#define CM2_SMEM   ((256*WH_STRIDE + 64*WH_STRIDE) * 4)

__device__ __forceinline__ void cm_stage_w(const float* __restrict__ Wg,
                                           uint32_t* __restrict__ Wh, int tid) {
    for (int idx = tid; idx < 256*32; idx += CM_THREADS) {
        int row = idx >> 5;
        int cg  = idx & 31;
        const float4* wp = reinterpret_cast<const float4*>(Wg + (size_t)row*C_ + cg*8);
        float4 u = wp[0], v = wp[1];
        __half2 h0 = __floats2half2_rn(u.x, u.y);
        __half2 h1 = __floats2half2_rn(u.z, u.w);
        __half2 h2 = __floats2half2_rn(v.x, v.y);
        __half2 h3 = __floats2half2_rn(v.z, v.w);
        *reinterpret_cast<uint4*>(Wh + row*WH_STRIDE + cg*4) =
            make_uint4(*(uint32_t*)&h0, *(uint32_t*)&h1, *(uint32_t*)&h2, *(uint32_t*)&h3);
    }
}

// HMMA path: warp wid<8, m-range [wm, wm+32), n-range [0, 48)
__device__ __forceinline__ void cm_gemm_hmma(const uint32_t* __restrict__ Xs,
                                             const uint32_t* __restrict__ Wh,
                                             int gid, int tig, int wm,
                                             float acc[2][6][4]) {
    #pragma unroll
    for (int i = 0; i < 2; i++)
        #pragma unroll
        for (int j = 0; j < 6; j++)
            #pragma unroll
            for (int r = 0; r < 4; r++) acc[i][j][r] = 0.f;

    #pragma unroll 4
    for (int k16 = 0; k16 < 16; k16++) {
        int kb = k16 * 8;
        uint32_t bfr[6][2];
        #pragma unroll
        for (int j = 0; j < 6; j++) {
            const uint32_t* xr = Xs + (j*8 + gid)*WH_STRIDE + kb;
            bfr[j][0] = xr[tig];
            bfr[j][1] = xr[tig + 4];
        }
        #pragma unroll
        for (int i = 0; i < 2; i++) {
            const uint32_t* wr  = Wh + (wm + i*16 + gid)*WH_STRIDE + kb;
            const uint32_t* wr8 = wr + 8*WH_STRIDE;
            uint32_t afr[4];
            afr[0] = wr[tig];
            afr[1] = wr8[tig];
            afr[2] = wr[tig + 4];
            afr[3] = wr8[tig + 4];
            #pragma unroll
            for (int j = 0; j < 6; j++)
                mma_f16(acc[i][j], afr, bfr[j]);
        }
    }
}

// FFMA path: threads 256-383. chb = base channel (0..31, stride-32 groups),
// tok = 48 + 4*(tid&3). Computes acc[q][t] = sum_k W[chb+32q][k]*X[tok+t][k].
__device__ __forceinline__ void cm_gemm_ffma(const __half* __restrict__ Xh,
                                             const __half* __restrict__ Whh,
                                             int chb, int tok,
                                             float acc[8][4]) {
    #pragma unroll
    for (int q = 0; q < 8; q++)
        #pragma unroll
        for (int t = 0; t < 4; t++) acc[q][t] = 0.f;

    #pragma unroll 4
    for (int k = 0; k < C_; k += 2) {
        float2 xv[4];
        #pragma unroll
        for (int t = 0; t < 4; t++) {
            __half2 hx = *reinterpret_cast<const __half2*>(Xh + (tok + t)*XROW_H + k);
            xv[t] = __half22float2(hx);
        }
        #pragma unroll
        for (int q = 0; q < 8; q++) {
            __half2 hw = *reinterpret_cast<const __half2*>(Whh + (chb + 32*q)*XROW_H + k);
            float2 wf = __half22float2(hw);
            #pragma unroll
            for (int t = 0; t < 4; t++)
                acc[q][t] = fmaf(wf.x, xv[t].x, fmaf(wf.y, xv[t].y, acc[q][t]));
        }
    }
}

__global__ void __launch_bounds__(CM_THREADS, 1)
cm1_kernel(const float* __restrict__ lng, const float* __restrict__ lnb,
           const float* __restrict__ W1,  const float* __restrict__ b1) {
    extern __shared__ uint32_t smu[];
    uint32_t* Wh   = smu;                          // [256][132]
    uint32_t* Xs   = Wh + 256*WH_STRIDE;           // [64][132]
    float* mu_s    = (float*)(Xs + 64*WH_STRIDE);  // [64]
    float* rs_s    = mu_s + 64;                    // [64]
    float* lg      = rs_s + 64;                    // [256]
    float* lb      = lg + 256;
    __half* Xh     = reinterpret_cast<__half*>(Xs);
    const __half* Whh = reinterpret_cast<const __half*>(Wh);

    const int tid  = threadIdx.x;
    const int b    = blockIdx.y;
    const int lane = tid & 31;
    const int wid  = tid >> 5;
    const int gid  = lane >> 2;
    const int tig  = lane & 3;
    const int wm   = wid * 32;                 // HMMA warps (wid<8)
    const int tidF = tid - 256;                // FFMA threads (wid>=8)
    const int chb  = (tidF >= 0) ? (tidF >> 2) : 0;
    const int tokF = HT_ + ((tidF & 3) << 2);

    cm_stage_w(W1, Wh, tid);
    if (tid < 256) { lg[tid] = lng[tid]; lb[tid] = lnb[tid]; }
    __syncthreads();

    for (int tile = blockIdx.x; tile < TILES_PB; tile += CM_GRIDX) {
        const int n0 = tile * 64;
        if (tid < 64) {
            float2 mr = g_murs[(size_t)b*N_ + n0 + tid];
            mu_s[tid] = mr.x;
            rs_s[tid] = mr.y;
        }
        __syncthreads();
        // ---- normalize into Xs (fp16 [n][k]) ----
        for (int idx = tid; idx < 4096; idx += CM_THREADS) {
            int rowN = idx >> 6;
            int f    = idx & 63;
            float4 v = *reinterpret_cast<const float4*>(
                g_tok2 + ((size_t)b*N_ + n0 + rowN)*C_ + f*4);
            float mu = mu_s[rowN], rs = rs_s[rowN];
            int c = f*4;
            __half2 h0 = __floats2half2_rn((v.x-mu)*rs*lg[c  ]+lb[c  ],
                                           (v.y-mu)*rs*lg[c+1]+lb[c+1]);
            __half2 h1 = __floats2half2_rn((v.z-mu)*rs*lg[c+2]+lb[c+2],
                                           (v.w-mu)*rs*lg[c+3]+lb[c+3]);
            uint2 u; u.x = *(uint32_t*)&h0; u.y = *(uint32_t*)&h1;
            *reinterpret_cast<uint2*>(Xs + rowN*WH_STRIDE + f*2) = u;
        }
        __syncthreads();

        // ---- dual-pipe GEMM1 ----
        float accH[2][6][4];
        float accF[8][4];
        if (wid < 8) cm_gemm_hmma(Xs, Wh, gid, tig, wm, accH);
        else         cm_gemm_ffma(Xh, Whh, chb, tokF, accF);
        __syncthreads();

        // ---- relu(h + b1) back into Xs ----
        if (wid < 8) {
            #pragma unroll
            for (int i = 0; i < 2; i++) {
                int m0 = wm + i*16 + gid;
                float bva = __ldg(b1 + m0);
                float bvb = __ldg(b1 + m0 + 8);
                #pragma unroll
                for (int j = 0; j < 6; j++) {
                    int col = j*8 + 2*tig;
                    Xh[ col   *XROW_H + m0    ] = __float2half(fmaxf(accH[i][j][0] + bva, 0.f));
                    Xh[(col+1)*XROW_H + m0    ] = __float2half(fmaxf(accH[i][j][1] + bva, 0.f));
                    Xh[ col   *XROW_H + m0 + 8] = __float2half(fmaxf(accH[i][j][2] + bvb, 0.f));
                    Xh[(col+1)*XROW_H + m0 + 8] = __float2half(fmaxf(accH[i][j][3] + bvb, 0.f));
                }
            }
        } else {
            #pragma unroll
            for (int q = 0; q < 8; q++) {
                int ch = chb + 32*q;
                float bv = __ldg(b1 + ch);
                #pragma unroll
                for (int t = 0; t < 4; t++)
                    Xh[(tokF + t)*XROW_H + ch] = __float2half(fmaxf(accF[q][t] + bv, 0.f));
            }
        }
        __syncthreads();

        // ---- dump h tile to g_h (token-major, coalesced) ----
        for (int idx = tid; idx < 64*32; idx += CM_THREADS) {
            int rowN = idx >> 5;
            int cg   = idx & 31;
            uint4 v = *reinterpret_cast<uint4*>(Xs + rowN*WH_STRIDE + cg*4);
            *reinterpret_cast<uint4*>(g_h + ((size_t)b*N_ + n0 + rowN)*C_ + cg*8) = v;
        }
        __syncthreads();
    }
}

__global__ void __launch_bounds__(CM_THREADS, 1)
cm2_kernel(const float* __restrict__ W2, const float* __restrict__ b2,
           const float* __restrict__ csc) {
    extern __shared__ uint32_t smu[];
    uint32_t* Wh = smu;                    // [256][132]
    uint32_t* Xs = Wh + 256*WH_STRIDE;     // [64][132]
    __half* Xh   = reinterpret_cast<__half*>(Xs);
    const __half* Whh = reinterpret_cast<const __half*>(Wh);

    const int tid  = threadIdx.x;
    const int b    = blockIdx.y;
    const int lane = tid & 31;
    const int wid  = tid >> 5;
    const int gid  = lane >> 2;
    const int tig  = lane & 3;
    const int wm   = wid * 32;
    const int tidF = tid - 256;
    const int chb  = (tidF >= 0) ? (tidF >> 2) : 0;
    const int tokF = HT_ + ((tidF & 3) << 2);

    cm_stage_w(W2, Wh, tid);
    __syncthreads();

    for (int tile = blockIdx.x; tile < TILES_PB; tile += CM_GRIDX) {
        const int n0 = tile * 64;
        for (int idx = tid; idx < 64*32; idx += CM_THREADS) {
            int rowN = idx >> 5;
            int cg   = idx & 31;
            uint4 v = *reinterpret_cast<const uint4*>(g_h + ((size_t)b*N_ + n0 + rowN)*C_ + cg*8);
            *reinterpret_cast<uint4*>(Xs + rowN*WH_STRIDE + cg*4) = v;
        }
        __syncthreads();

        // ---- dual-pipe GEMM2 ----
        float accH[2][6][4];
        float accF[8][4];
        if (wid < 8) cm_gemm_hmma(Xs, Wh, gid, tig, wm, accH);
        else         cm_gemm_ffma(Xh, Whh, chb, tokF, accF);
        __syncthreads();

        // ---- stage fp16 delta = (h2 + b2)*scale into Xs [n][c] ----
        if (wid < 8) {
            #pragma unroll
            for (int i = 0; i < 2; i++) {
                int m0 = wm + i*16 + gid;
                float b2a = __ldg(b2 + m0),     sca = __ldg(csc + m0);
                float b2b = __ldg(b2 + m0 + 8), scb = __ldg(csc + m0 + 8);
                #pragma unroll
                for (int j = 0; j < 6; j++) {
                    int col = j*8 + 2*tig;
                    Xh[ col   *XROW_H + m0    ] = __float2half((accH[i][j][0] + b2a) * sca);
                    Xh[(col+1)*XROW_H + m0    ] = __float2half((accH[i][j][1] + b2a) * sca);
                    Xh[ col   *XROW_H + m0 + 8] = __float2half((accH[i][j][2] + b2b) * scb);
                    Xh[(col+1)*XROW_H + m0 + 8] = __float2half((accH[i][j][3] + b2b) * scb);
                }
            }
        } else {
            #pragma unroll
            for (int q = 0; q < 8; q++) {
                int ch = chb + 32*q;
                float bv = __ldg(b2 + ch);
                float sc = __ldg(csc + ch);
                #pragma unroll
                for (int t = 0; t < 4; t++)
                    Xh[(tokF + t)*XROW_H + ch] = __float2half((accF[q][t] + bv) * sc);
            }
        }
        __syncthreads();

        // ---- coalesced tok2 += delta ----
        for (int idx = tid; idx < 4096; idx += CM_THREADS) {
            int rowN = idx >> 6;
            int f    = idx & 63;
            float* tp = g_tok2 + ((size_t)b*N_ + n0 + rowN)*C_ + f*4;
            float4 t = *reinterpret_cast<float4*>(tp);
            uint2 u = *reinterpret_cast<const uint2*>(Xs + rowN*WH_STRIDE + f*2);
            __half2 d0 = *reinterpret_cast<__half2*>(&u.x);
            __half2 d1 = *reinterpret_cast<__half2*>(&u.y);
            t.x += __low2float(d0);  t.y += __high2float(d0);
            t.z += __low2float(d1);  t.w += __high2float(d1);
            *reinterpret_cast<float4*>(tp) = t;
        }
        __syncthreads();
    }
}

// ---------------- launch ----------------
extern "C" void kernel_launch(void* const* d_in, const int* in_sizes, int n_in,
                              void* d_out, int out_size) {
    const float* tokens_in  = (const float*)d_in[0];
    const int*   cell_ind   = (const int*)  d_in[1];
    const float* occ        = (const float*)d_in[2];
    const float* smix_ln_g  = (const float*)d_in[3];
    const float* smix_ln_b  = (const float*)d_in[4];
    const float* ffn_w1     = (const float*)d_in[5];
    const float* ffn_b1     = (const float*)d_in[6];
    const float* ffn_w2     = (const float*)d_in[7];
    const float* ffn_b2     = (const float*)d_in[8];
    const float* att_scale  = (const float*)d_in[9];
    const float* att_bn_g   = (const float*)d_in[10];
    const float* att_bn_b   = (const float*)d_in[11];
    const float* cmix_ln_g  = (const float*)d_in[12];
    const float* cmix_ln_b  = (const float*)d_in[13];
    const float* cmix_w1    = (const float*)d_in[14];
    const float* cmix_b1    = (const float*)d_in[15];
    const float* cmix_w2    = (const float*)d_in[16];
    const float* cmix_b2    = (const float*)d_in[17];
    const float* cmix_scale = (const float*)d_in[18];
    float* tokens_out = (float*)d_out;

    cudaFuncSetAttribute(conv_cl_kernel, cudaFuncAttributeMaxDynamicSharedMemorySize, CONV_CL_SMEM);
    cudaFuncSetAttribute(cm1_kernel,     cudaFuncAttributeMaxDynamicSharedMemorySize, CM1_SMEM);
    cudaFuncSetAttribute(cm2_kernel,     cudaFuncAttributeMaxDynamicSharedMemorySize, CM2_SMEM);

    float* g_tok2_p;
    cudaGetSymbolAddress((void**)&g_tok2_p, g_tok2);

    cudaStream_t s2;
    cudaStreamCreateWithFlags(&s2, cudaStreamNonBlocking);
    cudaEvent_t evFork, evJoin;
    cudaEventCreateWithFlags(&evFork, cudaEventDisableTiming);
    cudaEventCreateWithFlags(&evJoin, cudaEventDisableTiming);

    cudaEventRecord(evFork, 0);
    cudaStreamWaitEvent(s2, evFork, 0);

    transpose_kernel<<<dim3(N_/32, 8, B_), dim3(32, 8), 0, s2>>>(tokens_in, g_tok2_p, C_, N_);

    zero_counts_kernel  <<<NCELLS/256, 256>>>();
    count_scatter_kernel<<<(B_*NG_*N_ + 255)/256, 256>>>(cell_ind, occ);
    wpt_kernel          <<<(B_*NG_*N_ + 255)/256, 256>>>(occ);
    scan1_kernel<<<384, 256>>>();
    scan2_kernel<<<1, 512>>>();
    scan3_kernel<<<384, 256>>>();
    fill_csr_kernel<<<(B_*NG_*N_ + 255)/256, 256>>>();

    cudaEventRecord(evJoin, s2);
    cudaStreamWaitEvent(0, evJoin, 0);

    for (int d = 0; d < DEPTH_; d++) {
        int g = d % NG_;

        ln_scatter_csr<<<dim3(HW_/8, B_), 256>>>(smix_ln_g + d*C_, smix_ln_b + d*C_, g);

        conv_cl_kernel<<<dim3(64, 8, B_), 256, CONV_CL_SMEM>>>(
            ffn_w1 + d*C_*9, ffn_b1 + d*C_,
            ffn_w2 + d*C_*9, ffn_b2 + d*C_,
            (d == 0) ? 1 : 0,
            (d == 3 && g == 0) ? 1 : 0);

        gather_v3<<<dim3(N_/8, B_), 256>>>(g, att_scale + d*C_,
                                           att_bn_g + d*C_, att_bn_b + d*C_);

        cm1_kernel<<<dim3(CM_GRIDX, B_), CM_THREADS, CM1_SMEM>>>(
            cmix_ln_g + d*C_, cmix_ln_b + d*C_,
            cmix_w1 + d*C_*C_, cmix_b1 + d*C_);

        cm2_kernel<<<dim3(CM_GRIDX, B_), CM_THREADS, CM2_SMEM>>>(
            cmix_w2 + d*C_*C_, cmix_b2 + d*C_, cmix_scale + d*C_);
    }

    transpose_kernel<<<dim3(8, N_/32, B_), dim3(32, 8)>>>(g_tok2_p, tokens_out, N_, C_);

    cudaEventDestroy(evFork);
    cudaEventDestroy(evJoin);
    cudaStreamDestroy(s2);
}

// round 16
// speedup vs baseline: 1.3579x; 1.3579x over previous
#include <cuda_runtime.h>
#include <cuda_fp16.h>
#include <math.h>
#include <stdint.h>

// ---------------- problem constants ----------------
#define B_     2
#define C_     256
#define N_     32768
#define H_     128
#define W_     128
#define HW_    16384
#define NG_    3
#define DEPTH_ 4
#define NCELLS (B_*NG_*HW_)    // 98304 = 384*256

// ---------------- device scratch (static, no allocs) ----------------
__device__ float g_grid2 [B_*HW_*C_];  // scatter target / conv input, [b][hw][c]
__device__ float g_plane2[B_*HW_*C_];  // conv output, [b][hw][c]
__device__ float g_skip2 [B_*HW_*C_];  // depth-0 plane snapshot, [b][hw][c]
__device__ float g_tok2  [(size_t)B_*N_*C_];  // working tokens, [b][n][c]
__device__ float g_wpt  [B_*NG_*N_];
__device__ int   g_ci   [B_*NG_*N_];
__device__ float g_counts[B_*NG_*HW_];
__device__ int   g_cnt [NCELLS];
__device__ int   g_off [NCELLS];
__device__ int   g_fill[NCELLS];
__device__ int   g_bsum[384];
__device__ int   g_bpre[384];
__device__ int   g_csr [B_*NG_*N_];
__device__ float g_bn_sum[C_];
__device__ float g_bn_sq [C_];
__device__ float2 g_murs[B_*N_];       // packed CM LayerNorm stats (mu, rstd)
__device__ __half g_h[(size_t)B_*N_*C_];   // relu(h1), fp16, [b][n][c]

// ---------------- helpers ----------------
__device__ __forceinline__ void mma_f16(float d[4], const uint32_t a[4], const uint32_t b[2]) {
    asm volatile(
        "mma.sync.aligned.m16n8k16.row.col.f32.f16.f16.f32 "
        "{%0,%1,%2,%3}, {%4,%5,%6,%7}, {%8,%9}, {%0,%1,%2,%3};\n"
        : "+f"(d[0]), "+f"(d[1]), "+f"(d[2]), "+f"(d[3])
        : "r"(a[0]), "r"(a[1]), "r"(a[2]), "r"(a[3]),
          "r"(b[0]), "r"(b[1]));
}

// ---------------- tiled transpose: src[R][C] -> dst[C][R] ----------------
__global__ void transpose_kernel(const float* __restrict__ src, float* __restrict__ dst,
                                 int R, int Cc) {
    __shared__ float t[32][33];
    int b = blockIdx.z;
    const float* s = src + (size_t)b*R*Cc;
    float* d = dst + (size_t)b*R*Cc;
    int c0 = blockIdx.x * 32;
    int r0 = blockIdx.y * 32;
    int tx = threadIdx.x, ty = threadIdx.y;   // (32, 8)
    #pragma unroll
    for (int i = ty; i < 32; i += 8)
        t[i][tx] = s[(size_t)(r0+i)*Cc + c0 + tx];
    __syncthreads();
    #pragma unroll
    for (int i = ty; i < 32; i += 8)
        d[(size_t)(c0+i)*R + r0 + tx] = t[tx][i];
}

// ---------------- projection weights + CSR build (once) ----------------
__global__ void zero_counts_kernel() {
    int i = blockIdx.x * blockDim.x + threadIdx.x;
    if (i < NCELLS) { g_counts[i] = 0.f; g_cnt[i] = 0; g_fill[i] = 0; }
}
__global__ void count_scatter_kernel(const int* __restrict__ cell_ind,
                                     const float* __restrict__ occ) {
    int i = blockIdx.x * blockDim.x + threadIdx.x;
    if (i >= B_*NG_*N_) return;
    int n = i % N_;
    int b = i / (NG_*N_);
    int ci = cell_ind[i];
    ci = min(max(ci, 0), HW_ - 1);
    g_ci[i] = ci;
    float o = occ[b*N_ + n];
    int cellflat = (i / N_)*HW_ + ci;
    atomicAdd(&g_counts[cellflat], o*o);
    atomicAdd(&g_cnt[cellflat], 1);
}
__global__ void wpt_kernel(const float* __restrict__ occ) {
    int i = blockIdx.x * blockDim.x + threadIdx.x;
    if (i >= B_*NG_*N_) return;
    int n = i % N_;
    int b = i / (NG_*N_);
    float o = occ[b*N_ + n];
    float cnt = g_counts[(i / N_)*HW_ + g_ci[i]];
    g_wpt[i] = o / (o*cnt + 1e-6f);
}
__global__ void scan1_kernel() {
    __shared__ int s[256];
    int i = blockIdx.x*256 + threadIdx.x;
    int v = g_cnt[i];
    s[threadIdx.x] = v;
    __syncthreads();
    #pragma unroll
    for (int o = 1; o < 256; o <<= 1) {
        int t = (threadIdx.x >= o) ? s[threadIdx.x - o] : 0;
        __syncthreads();
        s[threadIdx.x] += t;
        __syncthreads();
    }
    g_off[i] = s[threadIdx.x] - v;
    if (threadIdx.x == 255) g_bsum[blockIdx.x] = s[255];
}
__global__ void scan2_kernel() {
    __shared__ int s[512];
    int t = threadIdx.x;
    int v = (t < 384) ? g_bsum[t] : 0;
    s[t] = v;
    __syncthreads();
    #pragma unroll
    for (int o = 1; o < 512; o <<= 1) {
        int u = (t >= o) ? s[t - o] : 0;
        __syncthreads();
        s[t] += u;
        __syncthreads();
    }
    if (t < 384) g_bpre[t] = s[t] - v;
}
__global__ void scan3_kernel() {
    int i = blockIdx.x*256 + threadIdx.x;
    g_off[i] += g_bpre[blockIdx.x];
}
__global__ void fill_csr_kernel() {
    int i = blockIdx.x * blockDim.x + threadIdx.x;
    if (i >= B_*NG_*N_) return;
    int n = i % N_;
    int cellflat = (i / N_)*HW_ + g_ci[i];
    int slot = atomicAdd(&g_fill[cellflat], 1);
    g_csr[g_off[cellflat] + slot] = n;
}

// ---------------- SpatialMix: CSR warp-per-cell LN + single coalesced write ----------------
// block (0,0) also zeroes the BN accumulators for this depth (conv runs after).
__global__ void ln_scatter_csr(const float* __restrict__ lng,
                               const float* __restrict__ lnb,
                               int g) {
    __shared__ float4 sg[64], sb[64];
    int tid = threadIdx.x;
    if (blockIdx.x == 0 && blockIdx.y == 0) {
        g_bn_sum[tid] = 0.f;
        g_bn_sq[tid]  = 0.f;
    }
    if (tid < 64) {
        sg[tid] = reinterpret_cast<const float4*>(lng)[tid];
        sb[tid] = reinterpret_cast<const float4*>(lnb)[tid];
    }
    __syncthreads();

    int lane = tid & 31;
    int cell = blockIdx.x * 8 + (tid >> 5);
    int b = blockIdx.y;
    int cellflat = (b*NG_ + g)*HW_ + cell;
    int cnt = g_cnt[cellflat];
    int off = g_off[cellflat];

    float4 a0 = make_float4(0.f,0.f,0.f,0.f);
    float4 a1 = make_float4(0.f,0.f,0.f,0.f);
    float4 lg0 = sg[lane],      lb0 = sb[lane];
    float4 lg1 = sg[32 + lane], lb1 = sb[32 + lane];

    for (int k = 0; k < cnt; k++) {
        int n = g_csr[off + k];
        const float4* row = reinterpret_cast<const float4*>(g_tok2 + ((size_t)b*N_ + n)*C_);
        float4 v0 = row[lane];
        float4 v1 = row[32 + lane];
        float s  = v0.x + v0.y + v0.z + v0.w + v1.x + v1.y + v1.z + v1.w;
        float ss = v0.x*v0.x + v0.y*v0.y + v0.z*v0.z + v0.w*v0.w
                 + v1.x*v1.x + v1.y*v1.y + v1.z*v1.z + v1.w*v1.w;
        #pragma unroll
        for (int o = 16; o > 0; o >>= 1) {
            s  += __shfl_xor_sync(0xFFFFFFFFu, s,  o);
            ss += __shfl_xor_sync(0xFFFFFFFFu, ss, o);
        }
        float m    = s * (1.f / C_);
        float rstd = rsqrtf(ss * (1.f / C_) - m*m + 1e-5f);
        float w    = g_wpt[((size_t)b*NG_ + g)*N_ + n];

        a0.x += ((v0.x - m)*rstd*lg0.x + lb0.x)*w;
        a0.y += ((v0.y - m)*rstd*lg0.y + lb0.y)*w;
        a0.z += ((v0.z - m)*rstd*lg0.z + lb0.z)*w;
        a0.w += ((v0.w - m)*rstd*lg0.w + lb0.w)*w;
        a1.x += ((v1.x - m)*rstd*lg1.x + lb1.x)*w;
        a1.y += ((v1.y - m)*rstd*lg1.y + lb1.y)*w;
        a1.z += ((v1.z - m)*rstd*lg1.z + lb1.z)*w;
        a1.w += ((v1.w - m)*rstd*lg1.w + lb1.w)*w;
    }
    float4* gb = reinterpret_cast<float4*>(g_grid2 + ((size_t)b*HW_ + cell)*C_);
    gb[lane]      = a0;
    gb[32 + lane] = a1;
}

// ---------------- channel-last fused dwconv3x3 -> relu -> dwconv3x3 (+BN, +skip) ----------------
#define CONV_CL_SMEM ((400*32 + 324*32 + 288*2 + 64 + 64) * 4)
__global__ void __launch_bounds__(256, 2)
conv_cl_kernel(const float* __restrict__ w1g, const float* __restrict__ b1g,
               const float* __restrict__ w2g, const float* __restrict__ b2g,
               int save_skip, int add_skip) {
    extern __shared__ float cs[];
    float* sIn  = cs;               // [400][32]
    float* sMid = sIn + 400*32;     // [324][32]
    float* sW1  = sMid + 324*32;    // [9][32]
    float* sW2  = sW1 + 288;        // [9][32]
    float* sB   = sW2 + 288;        // [2][32]
    float* bnS  = sB + 64;          // [32]
    float* bnQ  = bnS + 32;         // [32]

    const int tid = threadIdx.x;
    const int cq  = tid & 7;
    const int pp  = tid >> 3;
    const int cg0 = blockIdx.y * 32;
    const int b   = blockIdx.z;
    const int oy  = (blockIdx.x >> 3) * 16;
    const int ox  = (blockIdx.x & 7) * 16;

    for (int i = tid; i < 288; i += 256) {
        int k = i >> 5, cc = i & 31;
        sW1[k*32 + cc] = w1g[(cg0+cc)*9 + k];
        sW2[k*32 + cc] = w2g[(cg0+cc)*9 + k];
    }
    if (tid < 32) {
        sB[tid]      = b1g[cg0 + tid];
        sB[32 + tid] = b2g[cg0 + tid];
        bnS[tid] = 0.f;
        bnQ[tid] = 0.f;
    }

    for (int i = pp; i < 400; i += 32) {
        int py = i / 20, px = i % 20;
        int gy = oy + py - 2, gx = ox + px - 2;
        float4 v = make_float4(0.f, 0.f, 0.f, 0.f);
        if (gy >= 0 && gy < H_ && gx >= 0 && gx < W_) {
            size_t off = ((size_t)b*HW_ + gy*W_ + gx)*C_ + cg0 + cq*4;
            v = *reinterpret_cast<const float4*>(g_grid2 + off);
            if (add_skip) {
                float4 s = *reinterpret_cast<const float4*>(g_skip2 + off);
                v.x += s.x; v.y += s.y; v.z += s.z; v.w += s.w;
            }
        }
        *reinterpret_cast<float4*>(sIn + i*32 + cq*4) = v;
    }
    float4 w1r[9];
    #pragma unroll
    for (int k = 0; k < 9; k++) w1r[k] = *reinterpret_cast<float4*>(sW1 + k*32 + cq*4);
    float4 b1v = *reinterpret_cast<float4*>(sB + cq*4);
    __syncthreads();

    for (int i = pp; i < 324; i += 32) {
        int my = i / 18, mx = i % 18;
        int gy = oy + my - 1, gx = ox + mx - 1;
        float4 acc = make_float4(0.f, 0.f, 0.f, 0.f);
        if (gy >= 0 && gy < H_ && gx >= 0 && gx < W_) {
            acc = b1v;
            #pragma unroll
            for (int ky = 0; ky < 3; ky++)
                #pragma unroll
                for (int kx = 0; kx < 3; kx++) {
                    const float4 u = *reinterpret_cast<float4*>(
                        sIn + ((my+ky)*20 + (mx+kx))*32 + cq*4);
                    const float4 wv = w1r[ky*3+kx];
                    acc.x += wv.x*u.x; acc.y += wv.y*u.y;
                    acc.z += wv.z*u.z; acc.w += wv.w*u.w;
                }
            acc.x = fmaxf(acc.x, 0.f); acc.y = fmaxf(acc.y, 0.f);
            acc.z = fmaxf(acc.z, 0.f); acc.w = fmaxf(acc.w, 0.f);
        }
        *reinterpret_cast<float4*>(sMid + i*32 + cq*4) = acc;
    }
    float4 w2r[9];
    #pragma unroll
    for (int k = 0; k < 9; k++) w2r[k] = *reinterpret_cast<float4*>(sW2 + k*32 + cq*4);
    float4 b2v = *reinterpret_cast<float4*>(sB + 32 + cq*4);
    __syncthreads();

    float4 psum = make_float4(0.f,0.f,0.f,0.f);
    float4 psq  = make_float4(0.f,0.f,0.f,0.f);
    for (int i = pp; i < 256; i += 32) {
        int dy = i >> 4, dx = i & 15;
        float4 acc = b2v;
        #pragma unroll
        for (int ky = 0; ky < 3; ky++)
            #pragma unroll
            for (int kx = 0; kx < 3; kx++) {
                const float4 u = *reinterpret_cast<float4*>(
                    sMid + ((dy+ky)*18 + (dx+kx))*32 + cq*4);
                const float4 wv = w2r[ky*3+kx];
                acc.x += wv.x*u.x; acc.y += wv.y*u.y;
                acc.z += wv.z*u.z; acc.w += wv.w*u.w;
            }
        size_t off = ((size_t)b*HW_ + (oy+dy)*W_ + ox+dx)*C_ + cg0 + cq*4;
        *reinterpret_cast<float4*>(g_plane2 + off) = acc;
        if (save_skip) *reinterpret_cast<float4*>(g_skip2 + off) = acc;
        psum.x += acc.x; psum.y += acc.y; psum.z += acc.z; psum.w += acc.w;
        psq.x += acc.x*acc.x; psq.y += acc.y*acc.y;
        psq.z += acc.z*acc.z; psq.w += acc.w*acc.w;
    }
    atomicAdd(&bnS[cq*4+0], psum.x); atomicAdd(&bnQ[cq*4+0], psq.x);
    atomicAdd(&bnS[cq*4+1], psum.y); atomicAdd(&bnQ[cq*4+1], psq.y);
    atomicAdd(&bnS[cq*4+2], psum.z); atomicAdd(&bnQ[cq*4+2], psq.z);
    atomicAdd(&bnS[cq*4+3], psum.w); atomicAdd(&bnQ[cq*4+3], psq.w);
    __syncthreads();
    if (tid < 32) {
        atomicAdd(&g_bn_sum[cg0 + tid], bnS[tid]);
        atomicAdd(&g_bn_sq [cg0 + tid], bnQ[tid]);
    }
}

// ---------------- gather: folded BN affine + gate + residual + CM LN stats ----------------
__global__ void gather_v3(int g,
                          const float* __restrict__ ascale,
                          const float* __restrict__ bng,
                          const float* __restrict__ bnb) {
    __shared__ float sA[C_], sB2[C_];
    int tid = threadIdx.x;
    {
        int c = tid;
        float s = __ldg(ascale + c);
        float m = g_bn_sum[c] * (1.f / (B_*HW_));
        float v = g_bn_sq[c]  * (1.f / (B_*HW_)) - m*m;
        float r = rsqrtf(s*s*v + 1e-5f);
        float gm = __ldg(bng + c);
        sA[c]  = s * r * gm;
        sB2[c] = __ldg(bnb + c) - s * m * r * gm;
    }
    __syncthreads();

    int lane = tid & 31;
    int n = blockIdx.x * 8 + (tid >> 5);
    int b = blockIdx.y;

    int cell = g_ci[((size_t)b*NG_ + g)*N_ + n];
    const float* pr = g_plane2 + ((size_t)b*HW_ + cell)*C_;
    float* tr = g_tok2 + ((size_t)b*N_ + n)*C_;

    int c0 = lane * 4;
    float s = 0.f, ss = 0.f;
    #pragma unroll
    for (int h = 0; h < 2; h++) {
        int c = c0 + h*128;
        float4 p = *reinterpret_cast<const float4*>(pr + c);
        float4 A = *reinterpret_cast<const float4*>(sA + c);
        float4 Bv = *reinterpret_cast<const float4*>(sB2 + c);
        float4 t = *reinterpret_cast<const float4*>(tr + c);
        t.x += p.x / (1.f + expf(-(p.x*A.x + Bv.x)));
        t.y += p.y / (1.f + expf(-(p.y*A.y + Bv.y)));
        t.z += p.z / (1.f + expf(-(p.z*A.z + Bv.z)));
        t.w += p.w / (1.f + expf(-(p.w*A.w + Bv.w)));
        s  += t.x + t.y + t.z + t.w;
        ss += t.x*t.x + t.y*t.y + t.z*t.z + t.w*t.w;
        *reinterpret_cast<float4*>(tr + c) = t;
    }
    #pragma unroll
    for (int o = 16; o > 0; o >>= 1) {
        s  += __shfl_xor_sync(0xFFFFFFFFu, s,  o);
        ss += __shfl_xor_sync(0xFFFFFFFFu, ss, o);
    }
    if (lane == 0) {
        float m = s * (1.f / C_);
        g_murs[(size_t)b*N_ + n] = make_float2(m, rsqrtf(ss * (1.f / C_) - m*m + 1e-5f));
    }
}

// ======================================================================
// ChannelMix (verified-best config): persistent-W, 256 threads,
// 8 warps 4m x 2n, warp tile 64m x 32n, scalar-LDS fragment fetch.
// cm1: normalize (packed mu/rs) -> GEMM1 -> relu -> g_h
// cm2: g_h -> GEMM2 -> fp16 delta staged -> coalesced tok2 RMW
// ======================================================================
#define WH_STRIDE  132
#define TILES_PB   (N_/64)
#define CM_GRIDX   74
#define CM1_SMEM   ((256*WH_STRIDE + 64*WH_STRIDE + 64 + 64 + 256 + 256) * 4)
#define CM2_SMEM   ((256*WH_STRIDE + 64*WH_STRIDE) * 4)

__device__ __forceinline__ void cm_stage_w(const float* __restrict__ Wg,
                                           uint32_t* __restrict__ Wh, int tid) {
    for (int idx = tid; idx < 256*32; idx += 256) {
        int row = idx >> 5;
        int cg  = idx & 31;
        const float4* wp = reinterpret_cast<const float4*>(Wg + (size_t)row*C_ + cg*8);
        float4 u = wp[0], v = wp[1];
        __half2 h0 = __floats2half2_rn(u.x, u.y);
        __half2 h1 = __floats2half2_rn(u.z, u.w);
        __half2 h2 = __floats2half2_rn(v.x, v.y);
        __half2 h3 = __floats2half2_rn(v.z, v.w);
        *reinterpret_cast<uint4*>(Wh + row*WH_STRIDE + cg*4) =
            make_uint4(*(uint32_t*)&h0, *(uint32_t*)&h1, *(uint32_t*)&h2, *(uint32_t*)&h3);
    }
}

__device__ __forceinline__ void cm_gemm_persist(const uint32_t* __restrict__ Xs,
                                                const uint32_t* __restrict__ Wh,
                                                int gid, int tig, int wm, int wn,
                                                float acc[4][4][4]) {
    #pragma unroll
    for (int i = 0; i < 4; i++)
        #pragma unroll
        for (int j = 0; j < 4; j++)
            #pragma unroll
            for (int r = 0; r < 4; r++) acc[i][j][r] = 0.f;

    #pragma unroll 4
    for (int k16 = 0; k16 < 16; k16++) {
        int kb = k16 * 8;
        uint32_t bfr[4][2];
        #pragma unroll
        for (int j = 0; j < 4; j++) {
            const uint32_t* xr = Xs + (wn + j*8 + gid)*WH_STRIDE + kb;
            bfr[j][0] = xr[tig];
            bfr[j][1] = xr[tig + 4];
        }
        #pragma unroll
        for (int i = 0; i < 4; i++) {
            const uint32_t* wr  = Wh + (wm + i*16 + gid)*WH_STRIDE + kb;
            const uint32_t* wr8 = wr + 8*WH_STRIDE;
            uint32_t afr[4];
            afr[0] = wr[tig];
            afr[1] = wr8[tig];
            afr[2] = wr[tig + 4];
            afr[3] = wr8[tig + 4];
            #pragma unroll
            for (int j = 0; j < 4; j++)
                mma_f16(acc[i][j], afr, bfr[j]);
        }
    }
}

__global__ void __launch_bounds__(256, 1)
cm1_kernel(const float* __restrict__ lng, const float* __restrict__ lnb,
           const float* __restrict__ W1,  const float* __restrict__ b1) {
    extern __shared__ uint32_t smu[];
    uint32_t* Wh   = smu;                          // [256][132]
    uint32_t* Xs   = Wh + 256*WH_STRIDE;           // [64][132]
    float* mu_s    = (float*)(Xs + 64*WH_STRIDE);  // [64]
    float* rs_s    = mu_s + 64;                    // [64]
    float* lg      = rs_s + 64;                    // [256]
    float* lb      = lg + 256;
    __half* Xh     = reinterpret_cast<__half*>(Xs);

    const int tid  = threadIdx.x;
    const int b    = blockIdx.y;
    const int lane = tid & 31;
    const int wid  = tid >> 5;
    const int gid  = lane >> 2;
    const int tig  = lane & 3;
    const int wm   = (wid >> 1) * 64;
    const int wn   = (wid & 1)  * 32;

    cm_stage_w(W1, Wh, tid);
    lg[tid] = lng[tid];
    lb[tid] = lnb[tid];
    __syncthreads();

    for (int tile = blockIdx.x; tile < TILES_PB; tile += CM_GRIDX) {
        const int n0 = tile * 64;
        if (tid < 64) {
            float2 mr = g_murs[(size_t)b*N_ + n0 + tid];
            mu_s[tid] = mr.x;
            rs_s[tid] = mr.y;
        }
        __syncthreads();
        // ---- normalize into Xs (fp16 [n][k]), token-major coalesced reads ----
        for (int idx = tid; idx < 4096; idx += 256) {
            int rowN = idx >> 6;
            int f    = idx & 63;
            float4 v = *reinterpret_cast<const float4*>(
                g_tok2 + ((size_t)b*N_ + n0 + rowN)*C_ + f*4);
            float mu = mu_s[rowN], rs = rs_s[rowN];
            int c = f*4;
            __half2 h0 = __floats2half2_rn((v.x-mu)*rs*lg[c  ]+lb[c  ],
                                           (v.y-mu)*rs*lg[c+1]+lb[c+1]);
            __half2 h1 = __floats2half2_rn((v.z-mu)*rs*lg[c+2]+lb[c+2],
                                           (v.w-mu)*rs*lg[c+3]+lb[c+3]);
            uint2 u; u.x = *(uint32_t*)&h0; u.y = *(uint32_t*)&h1;
            *reinterpret_cast<uint2*>(Xs + rowN*WH_STRIDE + f*2) = u;
        }
        __syncthreads();

        float acc[4][4][4];
        cm_gemm_persist(Xs, Wh, gid, tig, wm, wn, acc);
        __syncthreads();

        // ---- relu(h + b1) back into Xs ----
        #pragma unroll
        for (int i = 0; i < 4; i++) {
            int m0 = wm + i*16 + gid;
            float bva = __ldg(b1 + m0);
            float bvb = __ldg(b1 + m0 + 8);
            #pragma unroll
            for (int j = 0; j < 4; j++) {
                int col = wn + j*8 + 2*tig;
                Xh[ col   *(2*WH_STRIDE) + m0    ] = __float2half(fmaxf(acc[i][j][0] + bva, 0.f));
                Xh[(col+1)*(2*WH_STRIDE) + m0    ] = __float2half(fmaxf(acc[i][j][1] + bva, 0.f));
                Xh[ col   *(2*WH_STRIDE) + m0 + 8] = __float2half(fmaxf(acc[i][j][2] + bvb, 0.f));
                Xh[(col+1)*(2*WH_STRIDE) + m0 + 8] = __float2half(fmaxf(acc[i][j][3] + bvb, 0.f));
            }
        }
        __syncthreads();

        // ---- dump h tile to g_h (token-major, coalesced) ----
        for (int idx = tid; idx < 64*32; idx += 256) {
            int rowN = idx >> 5;
            int cg   = idx & 31;
            uint4 v = *reinterpret_cast<uint4*>(Xs + rowN*WH_STRIDE + cg*4);
            *reinterpret_cast<uint4*>(g_h + ((size_t)b*N_ + n0 + rowN)*C_ + cg*8) = v;
        }
        __syncthreads();
    }
}

__global__ void __launch_bounds__(256, 1)
cm2_kernel(const float* __restrict__ W2, const float* __restrict__ b2,
           const float* __restrict__ csc) {
    extern __shared__ uint32_t smu[];
    uint32_t* Wh = smu;                    // [256][132]
    uint32_t* Xs = Wh + 256*WH_STRIDE;     // [64][132]
    __half* Xh   = reinterpret_cast<__half*>(Xs);

    const int tid  = threadIdx.x;
    const int b    = blockIdx.y;
    const int lane = tid & 31;
    const int wid  = tid >> 5;
    const int gid  = lane >> 2;
    const int tig  = lane & 3;
    const int wm   = (wid >> 1) * 64;
    const int wn   = (wid & 1)  * 32;

    cm_stage_w(W2, Wh, tid);
    __syncthreads();

    for (int tile = blockIdx.x; tile < TILES_PB; tile += CM_GRIDX) {
        const int n0 = tile * 64;
        for (int idx = tid; idx < 64*32; idx += 256) {
            int rowN = idx >> 5;
            int cg   = idx & 31;
            uint4 v = *reinterpret_cast<const uint4*>(g_h + ((size_t)b*N_ + n0 + rowN)*C_ + cg*8);
            *reinterpret_cast<uint4*>(Xs + rowN*WH_STRIDE + cg*4) = v;
        }
        __syncthreads();

        float acc[4][4][4];
        cm_gemm_persist(Xs, Wh, gid, tig, wm, wn, acc);
        __syncthreads();

        // ---- stage fp16 delta = (h2 + b2)*scale into Xs [n][c] ----
        #pragma unroll
        for (int i = 0; i < 4; i++) {
            int m0 = wm + i*16 + gid;
            float b2a = __ldg(b2 + m0),     sca = __ldg(csc + m0);
            float b2b = __ldg(b2 + m0 + 8), scb = __ldg(csc + m0 + 8);
            #pragma unroll
            for (int j = 0; j < 4; j++) {
                int col = wn + j*8 + 2*tig;
                Xh[ col   *(2*WH_STRIDE) + m0    ] = __float2half((acc[i][j][0] + b2a) * sca);
                Xh[(col+1)*(2*WH_STRIDE) + m0    ] = __float2half((acc[i][j][1] + b2a) * sca);
                Xh[ col   *(2*WH_STRIDE) + m0 + 8] = __float2half((acc[i][j][2] + b2b) * scb);
                Xh[(col+1)*(2*WH_STRIDE) + m0 + 8] = __float2half((acc[i][j][3] + b2b) * scb);
            }
        }
        __syncthreads();

        // ---- coalesced tok2 += delta ----
        for (int idx = tid; idx < 4096; idx += 256) {
            int rowN = idx >> 6;
            int f    = idx & 63;
            float* tp = g_tok2 + ((size_t)b*N_ + n0 + rowN)*C_ + f*4;
            float4 t = *reinterpret_cast<float4*>(tp);
            uint2 u = *reinterpret_cast<const uint2*>(Xs + rowN*WH_STRIDE + f*2);
            __half2 d0 = *reinterpret_cast<__half2*>(&u.x);
            __half2 d1 = *reinterpret_cast<__half2*>(&u.y);
            t.x += __low2float(d0);  t.y += __high2float(d0);
            t.z += __low2float(d1);  t.w += __high2float(d1);
            *reinterpret_cast<float4*>(tp) = t;
        }
        __syncthreads();
    }
}

// ---------------- launch ----------------
extern "C" void kernel_launch(void* const* d_in, const int* in_sizes, int n_in,
                              void* d_out, int out_size) {
    const float* tokens_in  = (const float*)d_in[0];
    const int*   cell_ind   = (const int*)  d_in[1];
    const float* occ        = (const float*)d_in[2];
    const float* smix_ln_g  = (const float*)d_in[3];
    const float* smix_ln_b  = (const float*)d_in[4];
    const float* ffn_w1     = (const float*)d_in[5];
    const float* ffn_b1     = (const float*)d_in[6];
    const float* ffn_w2     = (const float*)d_in[7];
    const float* ffn_b2     = (const float*)d_in[8];
    const float* att_scale  = (const float*)d_in[9];
    const float* att_bn_g   = (const float*)d_in[10];
    const float* att_bn_b   = (const float*)d_in[11];
    const float* cmix_ln_g  = (const float*)d_in[12];
    const float* cmix_ln_b  = (const float*)d_in[13];
    const float* cmix_w1    = (const float*)d_in[14];
    const float* cmix_b1    = (const float*)d_in[15];
    const float* cmix_w2    = (const float*)d_in[16];
    const float* cmix_b2    = (const float*)d_in[17];
    const float* cmix_scale = (const float*)d_in[18];
    float* tokens_out = (float*)d_out;

    cudaFuncSetAttribute(conv_cl_kernel, cudaFuncAttributeMaxDynamicSharedMemorySize, CONV_CL_SMEM);
    cudaFuncSetAttribute(cm1_kernel,     cudaFuncAttributeMaxDynamicSharedMemorySize, CM1_SMEM);
    cudaFuncSetAttribute(cm2_kernel,     cudaFuncAttributeMaxDynamicSharedMemorySize, CM2_SMEM);

    float* g_tok2_p;
    cudaGetSymbolAddress((void**)&g_tok2_p, g_tok2);

    // side stream for setup overlap (host-side objects only; capture-legal fork/join)
    cudaStream_t s2;
    cudaStreamCreateWithFlags(&s2, cudaStreamNonBlocking);
    cudaEvent_t evFork, evJoin;
    cudaEventCreateWithFlags(&evFork, cudaEventDisableTiming);
    cudaEventCreateWithFlags(&evJoin, cudaEventDisableTiming);

    // fork: transpose-in on s2, CSR build chain on stream 0 (independent)
    cudaEventRecord(evFork, 0);
    cudaStreamWaitEvent(s2, evFork, 0);

    transpose_kernel<<<dim3(N_/32, 8, B_), dim3(32, 8), 0, s2>>>(tokens_in, g_tok2_p, C_, N_);

    zero_counts_kernel  <<<NCELLS/256, 256>>>();
    count_scatter_kernel<<<(B_*NG_*N_ + 255)/256, 256>>>(cell_ind, occ);
    wpt_kernel          <<<(B_*NG_*N_ + 255)/256, 256>>>(occ);
    scan1_kernel<<<384, 256>>>();
    scan2_kernel<<<1, 512>>>();
    scan3_kernel<<<384, 256>>>();
    fill_csr_kernel<<<(B_*NG_*N_ + 255)/256, 256>>>();

    cudaEventRecord(evJoin, s2);
    cudaStreamWaitEvent(0, evJoin, 0);

    for (int d = 0; d < DEPTH_; d++) {
        int g = d % NG_;

        ln_scatter_csr<<<dim3(HW_/8, B_), 256>>>(smix_ln_g + d*C_, smix_ln_b + d*C_, g);

        conv_cl_kernel<<<dim3(64, 8, B_), 256, CONV_CL_SMEM>>>(
            ffn_w1 + d*C_*9, ffn_b1 + d*C_,
            ffn_w2 + d*C_*9, ffn_b2 + d*C_,
            (d == 0) ? 1 : 0,
            (d == 3 && g == 0) ? 1 : 0);

        gather_v3<<<dim3(N_/8, B_), 256>>>(g, att_scale + d*C_,
                                           att_bn_g + d*C_, att_bn_b + d*C_);

        cm1_kernel<<<dim3(CM_GRIDX, B_), 256, CM1_SMEM>>>(
            cmix_ln_g + d*C_, cmix_ln_b + d*C_,
            cmix_w1 + d*C_*C_, cmix_b1 + d*C_);

        cm2_kernel<<<dim3(CM_GRIDX, B_), 256, CM2_SMEM>>>(
            cmix_w2 + d*C_*C_, cmix_b2 + d*C_, cmix_scale + d*C_);
    }

    // tok2 [b][n][c] -> d_out [b][c][n]
    transpose_kernel<<<dim3(8, N_/32, B_), dim3(32, 8)>>>(g_tok2_p, tokens_out, N_, C_);

    cudaEventDestroy(evFork);
    cudaEventDestroy(evJoin);
    cudaStreamDestroy(s2);
}

// round 17
// speedup vs baseline: 1.7341x; 1.2770x over previous
#include <cuda_runtime.h>
#include <cuda_fp16.h>
#include <math.h>
#include <stdint.h>

// ---------------- problem constants ----------------
#define B_     2
#define C_     256
#define N_     32768
#define H_     128
#define W_     128
#define HW_    16384
#define NG_    3
#define DEPTH_ 4
#define NCELLS (B_*NG_*HW_)    // 98304 = 384*256

// ---------------- device scratch (static, no allocs) ----------------
__device__ float g_grid2 [B_*HW_*C_];  // scatter target / conv input, [b][hw][c]
__device__ float g_plane2[B_*HW_*C_];  // conv output, [b][hw][c]
__device__ float g_skip2 [B_*HW_*C_];  // depth-0 plane snapshot, [b][hw][c]
__device__ float g_tok2  [(size_t)B_*N_*C_];  // working tokens, [b][n][c]
__device__ float g_wpt  [B_*NG_*N_];
__device__ int   g_ci   [B_*NG_*N_];
__device__ float g_counts[B_*NG_*HW_];
__device__ int   g_cnt [NCELLS];
__device__ int   g_off [NCELLS];
__device__ int   g_fill[NCELLS];
__device__ int   g_bsum[384];
__device__ int   g_bpre[384];
__device__ int   g_csr [B_*NG_*N_];
__device__ float g_bn_sum[C_];
__device__ float g_bn_sq [C_];
__device__ float2 g_murs[B_*N_];       // packed CM LayerNorm stats (mu, rstd)
__device__ __half g_h[(size_t)B_*N_*C_];   // relu(h1), fp16, [b][n][c]

// ---------------- helpers ----------------
__device__ __forceinline__ void mma_f16(float d[4], const uint32_t a[4], const uint32_t b[2]) {
    asm volatile(
        "mma.sync.aligned.m16n8k16.row.col.f32.f16.f16.f32 "
        "{%0,%1,%2,%3}, {%4,%5,%6,%7}, {%8,%9}, {%0,%1,%2,%3};\n"
        : "+f"(d[0]), "+f"(d[1]), "+f"(d[2]), "+f"(d[3])
        : "r"(a[0]), "r"(a[1]), "r"(a[2]), "r"(a[3]),
          "r"(b[0]), "r"(b[1]));
}

// ---------------- tiled transpose: src[R][C] -> dst[C][R] ----------------
__global__ void transpose_kernel(const float* __restrict__ src, float* __restrict__ dst,
                                 int R, int Cc) {
    __shared__ float t[32][33];
    int b = blockIdx.z;
    const float* s = src + (size_t)b*R*Cc;
    float* d = dst + (size_t)b*R*Cc;
    int c0 = blockIdx.x * 32;
    int r0 = blockIdx.y * 32;
    int tx = threadIdx.x, ty = threadIdx.y;   // (32, 8)
    #pragma unroll
    for (int i = ty; i < 32; i += 8)
        t[i][tx] = s[(size_t)(r0+i)*Cc + c0 + tx];
    __syncthreads();
    #pragma unroll
    for (int i = ty; i < 32; i += 8)
        d[(size_t)(c0+i)*R + r0 + tx] = t[tx][i];
}

// ---------------- projection weights + CSR build (once) ----------------
__global__ void zero_counts_kernel() {
    int i = blockIdx.x * blockDim.x + threadIdx.x;
    if (i < NCELLS) { g_counts[i] = 0.f; g_cnt[i] = 0; g_fill[i] = 0; }
}
__global__ void count_scatter_kernel(const int* __restrict__ cell_ind,
                                     const float* __restrict__ occ) {
    int i = blockIdx.x * blockDim.x + threadIdx.x;
    if (i >= B_*NG_*N_) return;
    int n = i % N_;
    int b = i / (NG_*N_);
    int ci = cell_ind[i];
    ci = min(max(ci, 0), HW_ - 1);
    g_ci[i] = ci;
    float o = occ[b*N_ + n];
    int cellflat = (i / N_)*HW_ + ci;
    atomicAdd(&g_counts[cellflat], o*o);
    atomicAdd(&g_cnt[cellflat], 1);
}
__global__ void wpt_kernel(const float* __restrict__ occ) {
    int i = blockIdx.x * blockDim.x + threadIdx.x;
    if (i >= B_*NG_*N_) return;
    int n = i % N_;
    int b = i / (NG_*N_);
    float o = occ[b*N_ + n];
    float cnt = g_counts[(i / N_)*HW_ + g_ci[i]];
    g_wpt[i] = o / (o*cnt + 1e-6f);
}
__global__ void scan1_kernel() {
    __shared__ int s[256];
    int i = blockIdx.x*256 + threadIdx.x;
    int v = g_cnt[i];
    s[threadIdx.x] = v;
    __syncthreads();
    #pragma unroll
    for (int o = 1; o < 256; o <<= 1) {
        int t = (threadIdx.x >= o) ? s[threadIdx.x - o] : 0;
        __syncthreads();
        s[threadIdx.x] += t;
        __syncthreads();
    }
    g_off[i] = s[threadIdx.x] - v;
    if (threadIdx.x == 255) g_bsum[blockIdx.x] = s[255];
}
__global__ void scan2_kernel() {
    __shared__ int s[512];
    int t = threadIdx.x;
    int v = (t < 384) ? g_bsum[t] : 0;
    s[t] = v;
    __syncthreads();
    #pragma unroll
    for (int o = 1; o < 512; o <<= 1) {
        int u = (t >= o) ? s[t - o] : 0;
        __syncthreads();
        s[t] += u;
        __syncthreads();
    }
    if (t < 384) g_bpre[t] = s[t] - v;
}
__global__ void scan3_kernel() {
    int i = blockIdx.x*256 + threadIdx.x;
    g_off[i] += g_bpre[blockIdx.x];
}
__global__ void fill_csr_kernel() {
    int i = blockIdx.x * blockDim.x + threadIdx.x;
    if (i >= B_*NG_*N_) return;
    int n = i % N_;
    int cellflat = (i / N_)*HW_ + g_ci[i];
    int slot = atomicAdd(&g_fill[cellflat], 1);
    g_csr[g_off[cellflat] + slot] = n;
}

// ---------------- SpatialMix: CSR warp-per-cell LN + single coalesced write ----------------
// block (0,0) also zeroes the BN accumulators for this depth (conv runs after).
__global__ void ln_scatter_csr(const float* __restrict__ lng,
                               const float* __restrict__ lnb,
                               int g) {
    __shared__ float4 sg[64], sb[64];
    int tid = threadIdx.x;
    if (blockIdx.x == 0 && blockIdx.y == 0) {
        g_bn_sum[tid] = 0.f;
        g_bn_sq[tid]  = 0.f;
    }
    if (tid < 64) {
        sg[tid] = reinterpret_cast<const float4*>(lng)[tid];
        sb[tid] = reinterpret_cast<const float4*>(lnb)[tid];
    }
    __syncthreads();

    int lane = tid & 31;
    int cell = blockIdx.x * 8 + (tid >> 5);
    int b = blockIdx.y;
    int cellflat = (b*NG_ + g)*HW_ + cell;
    int cnt = g_cnt[cellflat];
    int off = g_off[cellflat];

    float4 a0 = make_float4(0.f,0.f,0.f,0.f);
    float4 a1 = make_float4(0.f,0.f,0.f,0.f);
    float4 lg0 = sg[lane],      lb0 = sb[lane];
    float4 lg1 = sg[32 + lane], lb1 = sb[32 + lane];

    for (int k = 0; k < cnt; k++) {
        int n = g_csr[off + k];
        const float4* row = reinterpret_cast<const float4*>(g_tok2 + ((size_t)b*N_ + n)*C_);
        float4 v0 = row[lane];
        float4 v1 = row[32 + lane];
        float s  = v0.x + v0.y + v0.z + v0.w + v1.x + v1.y + v1.z + v1.w;
        float ss = v0.x*v0.x + v0.y*v0.y + v0.z*v0.z + v0.w*v0.w
                 + v1.x*v1.x + v1.y*v1.y + v1.z*v1.z + v1.w*v1.w;
        #pragma unroll
        for (int o = 16; o > 0; o >>= 1) {
            s  += __shfl_xor_sync(0xFFFFFFFFu, s,  o);
            ss += __shfl_xor_sync(0xFFFFFFFFu, ss, o);
        }
        float m    = s * (1.f / C_);
        float rstd = rsqrtf(ss * (1.f / C_) - m*m + 1e-5f);
        float w    = g_wpt[((size_t)b*NG_ + g)*N_ + n];

        a0.x += ((v0.x - m)*rstd*lg0.x + lb0.x)*w;
        a0.y += ((v0.y - m)*rstd*lg0.y + lb0.y)*w;
        a0.z += ((v0.z - m)*rstd*lg0.z + lb0.z)*w;
        a0.w += ((v0.w - m)*rstd*lg0.w + lb0.w)*w;
        a1.x += ((v1.x - m)*rstd*lg1.x + lb1.x)*w;
        a1.y += ((v1.y - m)*rstd*lg1.y + lb1.y)*w;
        a1.z += ((v1.z - m)*rstd*lg1.z + lb1.z)*w;
        a1.w += ((v1.w - m)*rstd*lg1.w + lb1.w)*w;
    }
    float4* gb = reinterpret_cast<float4*>(g_grid2 + ((size_t)b*HW_ + cell)*C_);
    gb[lane]      = a0;
    gb[32 + lane] = a1;
}

// ---------------- channel-last fused dwconv3x3 -> relu -> dwconv3x3 (+BN, +skip) ----------------
#define CONV_CL_SMEM ((400*32 + 324*32 + 288*2 + 64 + 64) * 4)
__global__ void __launch_bounds__(256, 2)
conv_cl_kernel(const float* __restrict__ w1g, const float* __restrict__ b1g,
               const float* __restrict__ w2g, const float* __restrict__ b2g,
               int save_skip, int add_skip) {
    extern __shared__ float cs[];
    float* sIn  = cs;               // [400][32]
    float* sMid = sIn + 400*32;     // [324][32]
    float* sW1  = sMid + 324*32;    // [9][32]
    float* sW2  = sW1 + 288;        // [9][32]
    float* sB   = sW2 + 288;        // [2][32]
    float* bnS  = sB + 64;          // [32]
    float* bnQ  = bnS + 32;         // [32]

    const int tid = threadIdx.x;
    const int cq  = tid & 7;
    const int pp  = tid >> 3;
    const int cg0 = blockIdx.y * 32;
    const int b   = blockIdx.z;
    const int oy  = (blockIdx.x >> 3) * 16;
    const int ox  = (blockIdx.x & 7) * 16;

    for (int i = tid; i < 288; i += 256) {
        int k = i >> 5, cc = i & 31;
        sW1[k*32 + cc] = w1g[(cg0+cc)*9 + k];
        sW2[k*32 + cc] = w2g[(cg0+cc)*9 + k];
    }
    if (tid < 32) {
        sB[tid]      = b1g[cg0 + tid];
        sB[32 + tid] = b2g[cg0 + tid];
        bnS[tid] = 0.f;
        bnQ[tid] = 0.f;
    }

    for (int i = pp; i < 400; i += 32) {
        int py = i / 20, px = i % 20;
        int gy = oy + py - 2, gx = ox + px - 2;
        float4 v = make_float4(0.f, 0.f, 0.f, 0.f);
        if (gy >= 0 && gy < H_ && gx >= 0 && gx < W_) {
            size_t off = ((size_t)b*HW_ + gy*W_ + gx)*C_ + cg0 + cq*4;
            v = *reinterpret_cast<const float4*>(g_grid2 + off);
            if (add_skip) {
                float4 s = *reinterpret_cast<const float4*>(g_skip2 + off);
                v.x += s.x; v.y += s.y; v.z += s.z; v.w += s.w;
            }
        }
        *reinterpret_cast<float4*>(sIn + i*32 + cq*4) = v;
    }
    float4 w1r[9];
    #pragma unroll
    for (int k = 0; k < 9; k++) w1r[k] = *reinterpret_cast<float4*>(sW1 + k*32 + cq*4);
    float4 b1v = *reinterpret_cast<float4*>(sB + cq*4);
    __syncthreads();

    for (int i = pp; i < 324; i += 32) {
        int my = i / 18, mx = i % 18;
        int gy = oy + my - 1, gx = ox + mx - 1;
        float4 acc = make_float4(0.f, 0.f, 0.f, 0.f);
        if (gy >= 0 && gy < H_ && gx >= 0 && gx < W_) {
            acc = b1v;
            #pragma unroll
            for (int ky = 0; ky < 3; ky++)
                #pragma unroll
                for (int kx = 0; kx < 3; kx++) {
                    const float4 u = *reinterpret_cast<float4*>(
                        sIn + ((my+ky)*20 + (mx+kx))*32 + cq*4);
                    const float4 wv = w1r[ky*3+kx];
                    acc.x += wv.x*u.x; acc.y += wv.y*u.y;
                    acc.z += wv.z*u.z; acc.w += wv.w*u.w;
                }
            acc.x = fmaxf(acc.x, 0.f); acc.y = fmaxf(acc.y, 0.f);
            acc.z = fmaxf(acc.z, 0.f); acc.w = fmaxf(acc.w, 0.f);
        }
        *reinterpret_cast<float4*>(sMid + i*32 + cq*4) = acc;
    }
    float4 w2r[9];
    #pragma unroll
    for (int k = 0; k < 9; k++) w2r[k] = *reinterpret_cast<float4*>(sW2 + k*32 + cq*4);
    float4 b2v = *reinterpret_cast<float4*>(sB + 32 + cq*4);
    __syncthreads();

    float4 psum = make_float4(0.f,0.f,0.f,0.f);
    float4 psq  = make_float4(0.f,0.f,0.f,0.f);
    for (int i = pp; i < 256; i += 32) {
        int dy = i >> 4, dx = i & 15;
        float4 acc = b2v;
        #pragma unroll
        for (int ky = 0; ky < 3; ky++)
            #pragma unroll
            for (int kx = 0; kx < 3; kx++) {
                const float4 u = *reinterpret_cast<float4*>(
                    sMid + ((dy+ky)*18 + (dx+kx))*32 + cq*4);
                const float4 wv = w2r[ky*3+kx];
                acc.x += wv.x*u.x; acc.y += wv.y*u.y;
                acc.z += wv.z*u.z; acc.w += wv.w*u.w;
            }
        size_t off = ((size_t)b*HW_ + (oy+dy)*W_ + ox+dx)*C_ + cg0 + cq*4;
        *reinterpret_cast<float4*>(g_plane2 + off) = acc;
        if (save_skip) *reinterpret_cast<float4*>(g_skip2 + off) = acc;
        psum.x += acc.x; psum.y += acc.y; psum.z += acc.z; psum.w += acc.w;
        psq.x += acc.x*acc.x; psq.y += acc.y*acc.y;
        psq.z += acc.z*acc.z; psq.w += acc.w*acc.w;
    }
    atomicAdd(&bnS[cq*4+0], psum.x); atomicAdd(&bnQ[cq*4+0], psq.x);
    atomicAdd(&bnS[cq*4+1], psum.y); atomicAdd(&bnQ[cq*4+1], psq.y);
    atomicAdd(&bnS[cq*4+2], psum.z); atomicAdd(&bnQ[cq*4+2], psq.z);
    atomicAdd(&bnS[cq*4+3], psum.w); atomicAdd(&bnQ[cq*4+3], psq.w);
    __syncthreads();
    if (tid < 32) {
        atomicAdd(&g_bn_sum[cg0 + tid], bnS[tid]);
        atomicAdd(&g_bn_sq [cg0 + tid], bnQ[tid]);
    }
}

// ---------------- gather: folded BN affine + gate + residual + CM LN stats ----------------
__global__ void gather_v3(int g,
                          const float* __restrict__ ascale,
                          const float* __restrict__ bng,
                          const float* __restrict__ bnb) {
    __shared__ float sA[C_], sB2[C_];
    int tid = threadIdx.x;
    {
        int c = tid;
        float s = __ldg(ascale + c);
        float m = g_bn_sum[c] * (1.f / (B_*HW_));
        float v = g_bn_sq[c]  * (1.f / (B_*HW_)) - m*m;
        float r = rsqrtf(s*s*v + 1e-5f);
        float gm = __ldg(bng + c);
        sA[c]  = s * r * gm;
        sB2[c] = __ldg(bnb + c) - s * m * r * gm;
    }
    __syncthreads();

    int lane = tid & 31;
    int n = blockIdx.x * 8 + (tid >> 5);
    int b = blockIdx.y;

    int cell = g_ci[((size_t)b*NG_ + g)*N_ + n];
    const float* pr = g_plane2 + ((size_t)b*HW_ + cell)*C_;
    float* tr = g_tok2 + ((size_t)b*N_ + n)*C_;

    int c0 = lane * 4;
    float s = 0.f, ss = 0.f;
    #pragma unroll
    for (int h = 0; h < 2; h++) {
        int c = c0 + h*128;
        float4 p = *reinterpret_cast<const float4*>(pr + c);
        float4 A = *reinterpret_cast<const float4*>(sA + c);
        float4 Bv = *reinterpret_cast<const float4*>(sB2 + c);
        float4 t = *reinterpret_cast<const float4*>(tr + c);
        t.x += p.x / (1.f + expf(-(p.x*A.x + Bv.x)));
        t.y += p.y / (1.f + expf(-(p.y*A.y + Bv.y)));
        t.z += p.z / (1.f + expf(-(p.z*A.z + Bv.z)));
        t.w += p.w / (1.f + expf(-(p.w*A.w + Bv.w)));
        s  += t.x + t.y + t.z + t.w;
        ss += t.x*t.x + t.y*t.y + t.z*t.z + t.w*t.w;
        *reinterpret_cast<float4*>(tr + c) = t;
    }
    #pragma unroll
    for (int o = 16; o > 0; o >>= 1) {
        s  += __shfl_xor_sync(0xFFFFFFFFu, s,  o);
        ss += __shfl_xor_sync(0xFFFFFFFFu, ss, o);
    }
    if (lane == 0) {
        float m = s * (1.f / C_);
        g_murs[(size_t)b*N_ + n] = make_float2(m, rsqrtf(ss * (1.f / C_) - m*m + 1e-5f));
    }
}

// ======================================================================
// ChannelMix (verified-best GEMM config) + SOFTWARE-PIPELINED global loads:
// all LDGs for the next phase are issued before the GEMM so their latency
// hides under the ~16k-cycle HMMA phase.
// cm1: prefetch next tile's tok2 across GEMM.
// cm2: prefetch next tile's g_h AND current tile's tok2 (RMW reads) across GEMM.
// ======================================================================
#define WH_STRIDE  132
#define TILES_PB   (N_/64)
#define CM_GRIDX   74
#define CM1_SMEM   ((256*WH_STRIDE + 64*WH_STRIDE + 64 + 64 + 256 + 256) * 4)
#define CM2_SMEM   ((256*WH_STRIDE + 64*WH_STRIDE) * 4)

__device__ __forceinline__ void cm_stage_w(const float* __restrict__ Wg,
                                           uint32_t* __restrict__ Wh, int tid) {
    for (int idx = tid; idx < 256*32; idx += 256) {
        int row = idx >> 5;
        int cg  = idx & 31;
        const float4* wp = reinterpret_cast<const float4*>(Wg + (size_t)row*C_ + cg*8);
        float4 u = wp[0], v = wp[1];
        __half2 h0 = __floats2half2_rn(u.x, u.y);
        __half2 h1 = __floats2half2_rn(u.z, u.w);
        __half2 h2 = __floats2half2_rn(v.x, v.y);
        __half2 h3 = __floats2half2_rn(v.z, v.w);
        *reinterpret_cast<uint4*>(Wh + row*WH_STRIDE + cg*4) =
            make_uint4(*(uint32_t*)&h0, *(uint32_t*)&h1, *(uint32_t*)&h2, *(uint32_t*)&h3);
    }
}

__device__ __forceinline__ void cm_gemm_persist(const uint32_t* __restrict__ Xs,
                                                const uint32_t* __restrict__ Wh,
                                                int gid, int tig, int wm, int wn,
                                                float acc[4][4][4]) {
    #pragma unroll
    for (int i = 0; i < 4; i++)
        #pragma unroll
        for (int j = 0; j < 4; j++)
            #pragma unroll
            for (int r = 0; r < 4; r++) acc[i][j][r] = 0.f;

    #pragma unroll 4
    for (int k16 = 0; k16 < 16; k16++) {
        int kb = k16 * 8;
        uint32_t bfr[4][2];
        #pragma unroll
        for (int j = 0; j < 4; j++) {
            const uint32_t* xr = Xs + (wn + j*8 + gid)*WH_STRIDE + kb;
            bfr[j][0] = xr[tig];
            bfr[j][1] = xr[tig + 4];
        }
        #pragma unroll
        for (int i = 0; i < 4; i++) {
            const uint32_t* wr  = Wh + (wm + i*16 + gid)*WH_STRIDE + kb;
            const uint32_t* wr8 = wr + 8*WH_STRIDE;
            uint32_t afr[4];
            afr[0] = wr[tig];
            afr[1] = wr8[tig];
            afr[2] = wr[tig + 4];
            afr[3] = wr8[tig + 4];
            #pragma unroll
            for (int j = 0; j < 4; j++)
                mma_f16(acc[i][j], afr, bfr[j]);
        }
    }
}

__global__ void __launch_bounds__(256, 1)
cm1_kernel(const float* __restrict__ lng, const float* __restrict__ lnb,
           const float* __restrict__ W1,  const float* __restrict__ b1) {
    extern __shared__ uint32_t smu[];
    uint32_t* Wh   = smu;                          // [256][132]
    uint32_t* Xs   = Wh + 256*WH_STRIDE;           // [64][132]
    float* mu_s    = (float*)(Xs + 64*WH_STRIDE);  // [64]
    float* rs_s    = mu_s + 64;                    // [64]
    float* lg      = rs_s + 64;                    // [256]
    float* lb      = lg + 256;
    __half* Xh     = reinterpret_cast<__half*>(Xs);

    const int tid  = threadIdx.x;
    const int b    = blockIdx.y;
    const int lane = tid & 31;
    const int wid  = tid >> 5;
    const int gid  = lane >> 2;
    const int tig  = lane & 3;
    const int wm   = (wid >> 1) * 64;
    const int wn   = (wid & 1)  * 32;

    cm_stage_w(W1, Wh, tid);
    lg[tid] = lng[tid];
    lb[tid] = lnb[tid];

    // prologue prefetch: first tile's tok2 rows
    int tile = blockIdx.x;
    float4 pf[16];
    if (tile < TILES_PB) {
        int n0 = tile * 64;
        #pragma unroll
        for (int q = 0; q < 16; q++) {
            int idx = tid + q*256;
            int rowN = idx >> 6, f = idx & 63;
            pf[q] = *reinterpret_cast<const float4*>(
                g_tok2 + ((size_t)b*N_ + n0 + rowN)*C_ + f*4);
        }
    }
    __syncthreads();

    for (; tile < TILES_PB; tile += CM_GRIDX) {
        const int n0 = tile * 64;
        if (tid < 64) {
            float2 mr = g_murs[(size_t)b*N_ + n0 + tid];
            mu_s[tid] = mr.x;
            rs_s[tid] = mr.y;
        }
        __syncthreads();   // stats ready; prev dump done (Xs free)

        // ---- normalize prefetched regs -> fp16 Xs (no LDG here) ----
        #pragma unroll
        for (int q = 0; q < 16; q++) {
            int idx = tid + q*256;
            int rowN = idx >> 6, f = idx & 63;
            float mu = mu_s[rowN], rs = rs_s[rowN];
            int c = f*4;
            float4 v = pf[q];
            __half2 h0 = __floats2half2_rn((v.x-mu)*rs*lg[c  ]+lb[c  ],
                                           (v.y-mu)*rs*lg[c+1]+lb[c+1]);
            __half2 h1 = __floats2half2_rn((v.z-mu)*rs*lg[c+2]+lb[c+2],
                                           (v.w-mu)*rs*lg[c+3]+lb[c+3]);
            uint2 u; u.x = *(uint32_t*)&h0; u.y = *(uint32_t*)&h1;
            *reinterpret_cast<uint2*>(Xs + rowN*WH_STRIDE + f*2) = u;
        }
        __syncthreads();

        // ---- prefetch NEXT tile's tok2 (latency hides under GEMM) ----
        int tn = tile + CM_GRIDX;
        if (tn < TILES_PB) {
            int n0n = tn * 64;
            #pragma unroll
            for (int q = 0; q < 16; q++) {
                int idx = tid + q*256;
                int rowN = idx >> 6, f = idx & 63;
                pf[q] = *reinterpret_cast<const float4*>(
                    g_tok2 + ((size_t)b*N_ + n0n + rowN)*C_ + f*4);
            }
        }

        float acc[4][4][4];
        cm_gemm_persist(Xs, Wh, gid, tig, wm, wn, acc);
        __syncthreads();

        // ---- relu(h + b1) back into Xs ----
        #pragma unroll
        for (int i = 0; i < 4; i++) {
            int m0 = wm + i*16 + gid;
            float bva = __ldg(b1 + m0);
            float bvb = __ldg(b1 + m0 + 8);
            #pragma unroll
            for (int j = 0; j < 4; j++) {
                int col = wn + j*8 + 2*tig;
                Xh[ col   *(2*WH_STRIDE) + m0    ] = __float2half(fmaxf(acc[i][j][0] + bva, 0.f));
                Xh[(col+1)*(2*WH_STRIDE) + m0    ] = __float2half(fmaxf(acc[i][j][1] + bva, 0.f));
                Xh[ col   *(2*WH_STRIDE) + m0 + 8] = __float2half(fmaxf(acc[i][j][2] + bvb, 0.f));
                Xh[(col+1)*(2*WH_STRIDE) + m0 + 8] = __float2half(fmaxf(acc[i][j][3] + bvb, 0.f));
            }
        }
        __syncthreads();

        // ---- dump h tile to g_h (token-major, coalesced) ----
        for (int idx = tid; idx < 64*32; idx += 256) {
            int rowN = idx >> 5;
            int cg   = idx & 31;
            uint4 v = *reinterpret_cast<uint4*>(Xs + rowN*WH_STRIDE + cg*4);
            *reinterpret_cast<uint4*>(g_h + ((size_t)b*N_ + n0 + rowN)*C_ + cg*8) = v;
        }
        __syncthreads();
    }
}

__global__ void __launch_bounds__(256, 1)
cm2_kernel(const float* __restrict__ W2, const float* __restrict__ b2,
           const float* __restrict__ csc) {
    extern __shared__ uint32_t smu[];
    uint32_t* Wh = smu;                    // [256][132]
    uint32_t* Xs = Wh + 256*WH_STRIDE;     // [64][132]
    __half* Xh   = reinterpret_cast<__half*>(Xs);

    const int tid  = threadIdx.x;
    const int b    = blockIdx.y;
    const int lane = tid & 31;
    const int wid  = tid >> 5;
    const int gid  = lane >> 2;
    const int tig  = lane & 3;
    const int wm   = (wid >> 1) * 64;
    const int wn   = (wid & 1)  * 32;

    cm_stage_w(W2, Wh, tid);

    // prologue prefetch: first tile's g_h
    int tile = blockIdx.x;
    uint4 pf[8];
    if (tile < TILES_PB) {
        int n0 = tile * 64;
        #pragma unroll
        for (int q = 0; q < 8; q++) {
            int idx = tid + q*256;
            int rowN = idx >> 5, cg = idx & 31;
            pf[q] = *reinterpret_cast<const uint4*>(
                g_h + ((size_t)b*N_ + n0 + rowN)*C_ + cg*8);
        }
    }
    __syncthreads();

    for (; tile < TILES_PB; tile += CM_GRIDX) {
        const int n0 = tile * 64;

        // ---- stage prefetched g_h tile into Xs ----
        #pragma unroll
        for (int q = 0; q < 8; q++) {
            int idx = tid + q*256;
            int rowN = idx >> 5, cg = idx & 31;
            *reinterpret_cast<uint4*>(Xs + rowN*WH_STRIDE + cg*4) = pf[q];
        }
        __syncthreads();

        // ---- prefetch NEXT tile's g_h + CURRENT tile's tok2 (hide under GEMM) ----
        int tn = tile + CM_GRIDX;
        if (tn < TILES_PB) {
            int n0n = tn * 64;
            #pragma unroll
            for (int q = 0; q < 8; q++) {
                int idx = tid + q*256;
                int rowN = idx >> 5, cg = idx & 31;
                pf[q] = *reinterpret_cast<const uint4*>(
                    g_h + ((size_t)b*N_ + n0n + rowN)*C_ + cg*8);
            }
        }
        float4 tf[16];
        #pragma unroll
        for (int q = 0; q < 16; q++) {
            int idx = tid + q*256;
            int rowN = idx >> 6, f = idx & 63;
            tf[q] = *reinterpret_cast<const float4*>(
                g_tok2 + ((size_t)b*N_ + n0 + rowN)*C_ + f*4);
        }

        float acc[4][4][4];
        cm_gemm_persist(Xs, Wh, gid, tig, wm, wn, acc);
        __syncthreads();

        // ---- stage fp16 delta = (h2 + b2)*scale into Xs [n][c] ----
        #pragma unroll
        for (int i = 0; i < 4; i++) {
            int m0 = wm + i*16 + gid;
            float b2a = __ldg(b2 + m0),     sca = __ldg(csc + m0);
            float b2b = __ldg(b2 + m0 + 8), scb = __ldg(csc + m0 + 8);
            #pragma unroll
            for (int j = 0; j < 4; j++) {
                int col = wn + j*8 + 2*tig;
                Xh[ col   *(2*WH_STRIDE) + m0    ] = __float2half((acc[i][j][0] + b2a) * sca);
                Xh[(col+1)*(2*WH_STRIDE) + m0    ] = __float2half((acc[i][j][1] + b2a) * sca);
                Xh[ col   *(2*WH_STRIDE) + m0 + 8] = __float2half((acc[i][j][2] + b2b) * scb);
                Xh[(col+1)*(2*WH_STRIDE) + m0 + 8] = __float2half((acc[i][j][3] + b2b) * scb);
            }
        }
        __syncthreads();

        // ---- tok2 += delta, using prefetched tok2 reads ----
        #pragma unroll
        for (int q = 0; q < 16; q++) {
            int idx = tid + q*256;
            int rowN = idx >> 6, f = idx & 63;
            float4 t = tf[q];
            uint2 u = *reinterpret_cast<const uint2*>(Xs + rowN*WH_STRIDE + f*2);
            __half2 d0 = *reinterpret_cast<__half2*>(&u.x);
            __half2 d1 = *reinterpret_cast<__half2*>(&u.y);
            t.x += __low2float(d0);  t.y += __high2float(d0);
            t.z += __low2float(d1);  t.w += __high2float(d1);
            *reinterpret_cast<float4*>(g_tok2 + ((size_t)b*N_ + n0 + rowN)*C_ + f*4) = t;
        }
        __syncthreads();
    }
}

// ---------------- launch ----------------
extern "C" void kernel_launch(void* const* d_in, const int* in_sizes, int n_in,
                              void* d_out, int out_size) {
    const float* tokens_in  = (const float*)d_in[0];
    const int*   cell_ind   = (const int*)  d_in[1];
    const float* occ        = (const float*)d_in[2];
    const float* smix_ln_g  = (const float*)d_in[3];
    const float* smix_ln_b  = (const float*)d_in[4];
    const float* ffn_w1     = (const float*)d_in[5];
    const float* ffn_b1     = (const float*)d_in[6];
    const float* ffn_w2     = (const float*)d_in[7];
    const float* ffn_b2     = (const float*)d_in[8];
    const float* att_scale  = (const float*)d_in[9];
    const float* att_bn_g   = (const float*)d_in[10];
    const float* att_bn_b   = (const float*)d_in[11];
    const float* cmix_ln_g  = (const float*)d_in[12];
    const float* cmix_ln_b  = (const float*)d_in[13];
    const float* cmix_w1    = (const float*)d_in[14];
    const float* cmix_b1    = (const float*)d_in[15];
    const float* cmix_w2    = (const float*)d_in[16];
    const float* cmix_b2    = (const float*)d_in[17];
    const float* cmix_scale = (const float*)d_in[18];
    float* tokens_out = (float*)d_out;

    cudaFuncSetAttribute(conv_cl_kernel, cudaFuncAttributeMaxDynamicSharedMemorySize, CONV_CL_SMEM);
    cudaFuncSetAttribute(cm1_kernel,     cudaFuncAttributeMaxDynamicSharedMemorySize, CM1_SMEM);
    cudaFuncSetAttribute(cm2_kernel,     cudaFuncAttributeMaxDynamicSharedMemorySize, CM2_SMEM);

    float* g_tok2_p;
    cudaGetSymbolAddress((void**)&g_tok2_p, g_tok2);

    // side stream for setup overlap (host-side objects only; capture-legal fork/join)
    cudaStream_t s2;
    cudaStreamCreateWithFlags(&s2, cudaStreamNonBlocking);
    cudaEvent_t evFork, evJoin;
    cudaEventCreateWithFlags(&evFork, cudaEventDisableTiming);
    cudaEventCreateWithFlags(&evJoin, cudaEventDisableTiming);

    cudaEventRecord(evFork, 0);
    cudaStreamWaitEvent(s2, evFork, 0);

    transpose_kernel<<<dim3(N_/32, 8, B_), dim3(32, 8), 0, s2>>>(tokens_in, g_tok2_p, C_, N_);

    zero_counts_kernel  <<<NCELLS/256, 256>>>();
    count_scatter_kernel<<<(B_*NG_*N_ + 255)/256, 256>>>(cell_ind, occ);
    wpt_kernel          <<<(B_*NG_*N_ + 255)/256, 256>>>(occ);
    scan1_kernel<<<384, 256>>>();
    scan2_kernel<<<1, 512>>>();
    scan3_kernel<<<384, 256>>>();
    fill_csr_kernel<<<(B_*NG_*N_ + 255)/256, 256>>>();

    cudaEventRecord(evJoin, s2);
    cudaStreamWaitEvent(0, evJoin, 0);

    for (int d = 0; d < DEPTH_; d++) {
        int g = d % NG_;

        ln_scatter_csr<<<dim3(HW_/8, B_), 256>>>(smix_ln_g + d*C_, smix_ln_b + d*C_, g);

        conv_cl_kernel<<<dim3(64, 8, B_), 256, CONV_CL_SMEM>>>(
            ffn_w1 + d*C_*9, ffn_b1 + d*C_,
            ffn_w2 + d*C_*9, ffn_b2 + d*C_,
            (d == 0) ? 1 : 0,
            (d == 3 && g == 0) ? 1 : 0);

        gather_v3<<<dim3(N_/8, B_), 256>>>(g, att_scale + d*C_,
                                           att_bn_g + d*C_, att_bn_b + d*C_);

        cm1_kernel<<<dim3(CM_GRIDX, B_), 256, CM1_SMEM>>>(
            cmix_ln_g + d*C_, cmix_ln_b + d*C_,
            cmix_w1 + d*C_*C_, cmix_b1 + d*C_);

        cm2_kernel<<<dim3(CM_GRIDX, B_), 256, CM2_SMEM>>>(
            cmix_w2 + d*C_*C_, cmix_b2 + d*C_, cmix_scale + d*C_);
    }

    // tok2 [b][n][c] -> d_out [b][c][n]
    transpose_kernel<<<dim3(8, N_/32, B_), dim3(32, 8)>>>(g_tok2_p, tokens_out, N_, C_);

    cudaEventDestroy(evFork);
    cudaEventDestroy(evJoin);
    cudaStreamDestroy(s2);
}